// round 4
// baseline (speedup 1.0000x reference)
#include <cuda_runtime.h>
#include <math.h>

// ---------------- problem constants ----------------
namespace {
constexpr int B_   = 8;
constexpr int IMG_ = 128;
constexpr int D_   = 128;
constexpr int H_   = 4;
constexpr int HD_  = 32;
constexpr int L_   = 2;
constexpr int NC_  = 256;   // 16x16 coarse tokens
constexpr int NF_  = 1024;  // 32x32 fine tokens
constexpr int N_   = 1280;  // NC+NF
constexpr int OUT_ = 32;
constexpr float SCALE_ = 0.17677669529663687f; // 32^-0.5
}

// ---------------- packed f32x2 helpers (sm_103a FFMA2 path) ----------------
typedef unsigned long long u64;

__device__ __forceinline__ u64 pack2(float lo, float hi) {
    u64 r; asm("mov.b64 %0, {%1, %2};" : "=l"(r) : "f"(lo), "f"(hi)); return r;
}
__device__ __forceinline__ void unpack2(u64 v, float& lo, float& hi) {
    asm("mov.b64 {%0, %1}, %2;" : "=f"(lo), "=f"(hi) : "l"(v));
}
__device__ __forceinline__ u64 fma2(u64 a, u64 b, u64 c) {
    u64 r; asm("fma.rn.f32x2 %0, %1, %2, %3;" : "=l"(r) : "l"(a), "l"(b), "l"(c)); return r;
}
__device__ __forceinline__ u64 mul2(u64 a, u64 b) {
    u64 r; asm("mul.rn.f32x2 %0, %1, %2;" : "=l"(r) : "l"(a), "l"(b)); return r;
}

// ---------------- scratch (static device globals; no allocations) ----------------
__device__ float g_fine  [B_*NF_*D_];
__device__ float g_tokens[B_*N_*D_];
__device__ float g_y     [B_*N_*D_];
__device__ float g_qkv   [B_*N_*3*D_];
__device__ float g_att   [B_*N_*D_];
__device__ float g_h1    [B_*N_*2*D_];
__device__ float g_e     [B_*NF_];
__device__ int   g_mask  [B_*NF_];
__device__ int   g_order [B_*NF_];
__device__ int   g_ntrue [B_];
__device__ float g_c     [B_*NC_];
__device__ float g_fmap  [B_*NF_];
__device__ float g_fused [B_*2*OUT_*OUT_];
__device__ float g_hb    [B_*2*OUT_*OUT_];

// ---------------- patch embeds ----------------
__global__ void k_coarse(const float* __restrict__ x, const float* __restrict__ Wpc,
                         const float* __restrict__ bpc, const float* __restrict__ te) {
    __shared__ float sp[64];
    int blk = blockIdx.x;
    int b = blk >> 8, tok = blk & 255;
    int i = tok >> 4, j = tok & 15;
    int t = threadIdx.x;
    if (t < 64) {
        int pr = t >> 3, pc = t & 7;
        sp[t] = x[(b*IMG_ + i*8 + pr)*IMG_ + j*8 + pc];
    }
    __syncthreads();
    float acc = 0.f;
    #pragma unroll
    for (int p = 0; p < 64; p++) acc += sp[p] * Wpc[p*D_ + t];
    g_tokens[((size_t)b*N_ + tok)*D_ + t] = acc + bpc[t] + te[t];
}

__global__ void k_fine(const float* __restrict__ x, const float* __restrict__ Wpf,
                       const float* __restrict__ bpf) {
    __shared__ float sp[16];
    int blk = blockIdx.x;
    int b = blk >> 10, tok = blk & 1023;
    int i = tok >> 5, j = tok & 31;
    int t = threadIdx.x;
    if (t < 16) {
        int pr = t >> 2, pc = t & 3;
        sp[t] = x[(b*IMG_ + i*4 + pr)*IMG_ + j*4 + pc];
    }
    __syncthreads();
    float acc = 0.f;
    #pragma unroll
    for (int p = 0; p < 16; p++) acc += sp[p] * Wpf[p*D_ + t];
    g_fine[((size_t)b*NF_ + tok)*D_ + t] = acc + bpf[t];
}

// ---------------- edge map: sobel -> 4x4 avgpool ----------------
__device__ __forceinline__ float xat(const float* x, int b, int y, int c) {
    if ((unsigned)y >= (unsigned)IMG_ || (unsigned)c >= (unsigned)IMG_) return 0.f;
    return x[(b*IMG_ + y)*IMG_ + c];
}

__global__ void k_edge(const float* __restrict__ x) {
    int idx = blockIdx.x*blockDim.x + threadIdx.x;
    if (idx >= B_*NF_) return;
    int b = idx >> 10, cell = idx & 1023;
    int yi = cell >> 5, xi = cell & 31;
    float acc = 0.f;
    for (int dy = 0; dy < 4; dy++)
    for (int dx = 0; dx < 4; dx++) {
        int py = yi*4 + dy, px = xi*4 + dx;
        float a  = xat(x,b,py-1,px-1), bv = xat(x,b,py-1,px), c  = xat(x,b,py-1,px+1);
        float d  = xat(x,b,py  ,px-1),                         e2 = xat(x,b,py  ,px+1);
        float f  = xat(x,b,py+1,px-1), g  = xat(x,b,py+1,px), h2 = xat(x,b,py+1,px+1);
        float gx = -a + c - 2.f*d + 2.f*e2 - f + h2;
        float gy = -a - 2.f*bv - c + f + 2.f*g + h2;
        acc += sqrtf(gx*gx + gy*gy);
    }
    g_e[idx] = acc * (1.f/16.f);
}

__global__ void k_mask() {
    int b = blockIdx.x, t = threadIdx.x;   // 256 threads
    __shared__ float sh[256];
    float s = 0.f;
    for (int i = t; i < NF_; i += 256) s += g_e[b*NF_ + i];
    sh[t] = s; __syncthreads();
    for (int o = 128; o; o >>= 1) { if (t < o) sh[t] += sh[t+o]; __syncthreads(); }
    float mean = sh[0] * (1.f/NF_);
    for (int i = t; i < NF_; i += 256)
        g_mask[b*NF_ + i] = (g_e[b*NF_ + i] > mean) ? 1 : 0;
}

// stable argsort of !mask via prefix sum: edge tokens first, pixel order preserved
__global__ void k_order() {
    int b = blockIdx.x, t = threadIdx.x;   // 1024 threads
    __shared__ int sh[1024];
    int m = g_mask[b*NF_ + t];
    sh[t] = m; __syncthreads();
    for (int o = 1; o < 1024; o <<= 1) {
        int v = (t >= o) ? sh[t-o] : 0;
        __syncthreads();
        sh[t] += v;
        __syncthreads();
    }
    int incl = sh[t];
    int total = sh[1023];
    int pos = m ? (incl - 1) : (total + t - incl);
    g_order[b*NF_ + pos] = t;
    if (t == 0) g_ntrue[b] = total;
}

__global__ void k_assemble(const float* __restrict__ te) {
    int blk = blockIdx.x;
    int b = blk >> 10, pos = blk & 1023;
    int t = threadIdx.x;
    float v = te[D_ + t];
    if (pos < g_ntrue[b])
        v += g_fine[((size_t)b*NF_ + g_order[b*NF_ + pos])*D_ + t];
    g_tokens[((size_t)b*N_ + NC_ + pos)*D_ + t] = v;
}

// ---------------- layernorm (one block per token row, D=128) ----------------
__global__ void k_ln(const float* __restrict__ in, const float* __restrict__ g,
                     const float* __restrict__ bb, float* __restrict__ out) {
    int row = blockIdx.x, t = threadIdx.x;
    float v = in[(size_t)row*D_ + t];
    float s = v, q = v*v;
    #pragma unroll
    for (int o = 16; o; o >>= 1) {
        s += __shfl_xor_sync(~0u, s, o);
        q += __shfl_xor_sync(~0u, q, o);
    }
    __shared__ float ss[4], sq[4];
    int w = t >> 5, lane = t & 31;
    if (lane == 0) { ss[w] = s; sq[w] = q; }
    __syncthreads();
    s = ss[0]+ss[1]+ss[2]+ss[3];
    q = sq[0]+sq[1]+sq[2]+sq[3];
    float mean = s * (1.f/D_);
    float var  = q * (1.f/D_) - mean*mean;
    out[(size_t)row*D_ + t] = (v - mean) * rsqrtf(var + 1e-5f) * g[t] + bb[t];
}

// ---------------- SGEMM with packed f32x2: C = act(A@W + bias) + res ----------------
// 64x64 block tile, BK=16, 256 threads, 4x4 micro-tile.
// B tile is stored into smem PRE-DUPLICATED as (b,b) u64 pairs so the FFMA2
// broadcast operand needs no per-iteration pack movs. A pairs come free from float4.
__global__ __launch_bounds__(256) void sgemm(
    const float* __restrict__ A, const float* __restrict__ Bw,
    const float* __restrict__ bias, const float* __restrict__ res,
    float* __restrict__ C, int M, int Nn, int K, int act)
{
    __shared__ __align__(16) float As[16][64];
    __shared__ __align__(16) u64   Bs2[16][64];   // Bs2[k][n] = (b, b) duplicated
    int t = threadIdx.x;
    int m0 = blockIdx.y*64, n0 = blockIdx.x*64;
    int ty = t >> 4, tx = t & 15;
    u64 acc[4][2];
    #pragma unroll
    for (int i = 0; i < 4; i++) { acc[i][0] = 0ull; acc[i][1] = 0ull; }

    for (int k0 = 0; k0 < K; k0 += 16) {
        {
            int idx = t*4;
            int ar = idx >> 4, ac = idx & 15;
            float4 v = *(const float4*)(A + (size_t)(m0+ar)*K + k0 + ac);
            As[ac  ][ar] = v.x; As[ac+1][ar] = v.y;
            As[ac+2][ar] = v.z; As[ac+3][ar] = v.w;
        }
        {
            int idx = t*4;
            int br = idx >> 6, bc = idx & 63;
            float4 v = *(const float4*)(Bw + (size_t)(k0+br)*Nn + n0 + bc);
            Bs2[br][bc  ] = pack2(v.x, v.x);
            Bs2[br][bc+1] = pack2(v.y, v.y);
            Bs2[br][bc+2] = pack2(v.z, v.z);
            Bs2[br][bc+3] = pack2(v.w, v.w);
        }
        __syncthreads();
        #pragma unroll
        for (int kk = 0; kk < 16; kk++) {
            float4 af = *(const float4*)&As[kk][ty*4];     // a0..a3
            u64 a01 = pack2(af.x, af.y);                   // (a0,a1)
            u64 a23 = pack2(af.z, af.w);                   // (a2,a3)
            const u64* bp = &Bs2[kk][tx*4];
            u64 b0 = bp[0], b1 = bp[1], b2 = bp[2], b3 = bp[3];
            acc[0][0] = fma2(a01, b0, acc[0][0]);   // (a0*b0, a1*b0) -> rows 0,1 col 0
            acc[0][1] = fma2(a23, b0, acc[0][1]);   // rows 2,3 col 0
            acc[1][0] = fma2(a01, b1, acc[1][0]);
            acc[1][1] = fma2(a23, b1, acc[1][1]);
            acc[2][0] = fma2(a01, b2, acc[2][0]);
            acc[2][1] = fma2(a23, b2, acc[2][1]);
            acc[3][0] = fma2(a01, b3, acc[3][0]);
            acc[3][1] = fma2(a23, b3, acc[3][1]);
        }
        __syncthreads();
    }
    // acc[j][p] holds (C[rowpair], .) for col n0+tx*4+j, rows m0+ty*4 + 2p, +2p+1
    #pragma unroll
    for (int j = 0; j < 4; j++) {
        int n = n0 + tx*4 + j;
        #pragma unroll
        for (int p = 0; p < 2; p++) {
            float vlo, vhi;
            unpack2(acc[j][p], vlo, vhi);
            #pragma unroll
            for (int q = 0; q < 2; q++) {
                int m = m0 + ty*4 + p*2 + q;
                float v = q ? vhi : vlo;
                if (bias) v += bias[n];
                if (act == 1) v = 0.5f * v * (1.f + erff(v * 0.70710678118654752f));
                if (res)  v += res[(size_t)m*Nn + n];
                C[(size_t)m*Nn + n] = v;
            }
        }
    }
}

// ---------------- attention: online softmax, f32x2 packed over d-pairs ----------------
// 32 q / block, 2 q / thread; K/V rows consumed directly as (f32,f32) u64 pairs.
__global__ __launch_bounds__(128) void k_attn(const float* __restrict__ qkv,
                                              float* __restrict__ out) {
    __shared__ __align__(16) float Ks[64][36];
    __shared__ __align__(16) float Vs[64][36];
    __shared__ float red[128*34];
    int b = blockIdx.z, h = blockIdx.y, q0 = blockIdx.x*32;
    int t = threadIdx.x;
    int j = t & 7, qp = t >> 3;
    int qa = q0 + qp*2;

    const float* qptr = qkv + ((size_t)b*N_ + qa)*384 + h*32;
    u64 qA[16], qB[16];           // queries pre-scaled, packed over d-pairs
    #pragma unroll
    for (int d = 0; d < 32; d += 2) {
        qA[d>>1] = pack2(qptr[d]*SCALE_,     qptr[d+1]*SCALE_);
        qB[d>>1] = pack2(qptr[384+d]*SCALE_, qptr[384+d+1]*SCALE_);
    }

    float m0 = -1e30f, s0 = 0.f, m1 = -1e30f, s1 = 0.f;
    u64 acc0[16], acc1[16];
    #pragma unroll
    for (int i = 0; i < 16; i++) { acc0[i] = 0ull; acc1[i] = 0ull; }

    for (int k0 = 0; k0 < N_; k0 += 64) {
        __syncthreads();
        for (int i = t; i < 512; i += 128) {
            int key = i >> 3, dq = (i & 7) << 2;
            const float* kp = qkv + ((size_t)b*N_ + k0 + key)*384 + 128 + h*32 + dq;
            float4 kv = *(const float4*)kp;
            Ks[key][dq] = kv.x; Ks[key][dq+1] = kv.y; Ks[key][dq+2] = kv.z; Ks[key][dq+3] = kv.w;
            float4 vv = *(const float4*)(kp + 128);
            Vs[key][dq] = vv.x; Vs[key][dq+1] = vv.y; Vs[key][dq+2] = vv.z; Vs[key][dq+3] = vv.w;
        }
        __syncthreads();
        for (int kk = j; kk < 64; kk += 8) {
            u64 dA = 0ull, dB = 0ull;
            #pragma unroll
            for (int i = 0; i < 16; i += 2) {
                ulonglong2 kv = *(const ulonglong2*)&Ks[kk][i*2];
                dA = fma2(qA[i],   kv.x, dA);
                dA = fma2(qA[i+1], kv.y, dA);
                dB = fma2(qB[i],   kv.x, dB);
                dB = fma2(qB[i+1], kv.y, dB);
            }
            float lo, hi;
            unpack2(dA, lo, hi); float d0 = lo + hi;
            unpack2(dB, lo, hi); float d1 = lo + hi;

            if (d0 > m0) {
                float f = __expf(m0 - d0); s0 *= f;
                u64 ff = pack2(f, f);
                #pragma unroll
                for (int i = 0; i < 16; i++) acc0[i] = mul2(acc0[i], ff);
                m0 = d0;
            }
            float p0 = __expf(d0 - m0); s0 += p0;
            if (d1 > m1) {
                float f = __expf(m1 - d1); s1 *= f;
                u64 ff = pack2(f, f);
                #pragma unroll
                for (int i = 0; i < 16; i++) acc1[i] = mul2(acc1[i], ff);
                m1 = d1;
            }
            float p1 = __expf(d1 - m1); s1 += p1;

            u64 pp0 = pack2(p0, p0), pp1 = pack2(p1, p1);
            #pragma unroll
            for (int i = 0; i < 16; i += 2) {
                ulonglong2 vv = *(const ulonglong2*)&Vs[kk][i*2];
                acc0[i]   = fma2(pp0, vv.x, acc0[i]);
                acc0[i+1] = fma2(pp0, vv.y, acc0[i+1]);
                acc1[i]   = fma2(pp1, vv.x, acc1[i]);
                acc1[i+1] = fma2(pp1, vv.y, acc1[i+1]);
            }
        }
    }

    float* r = red + t*34;
    for (int pass = 0; pass < 2; pass++) {
        __syncthreads();
        r[0] = pass ? m1 : m0;
        r[1] = pass ? s1 : s0;
        #pragma unroll
        for (int i = 0; i < 16; i++) {
            float lo, hi;
            unpack2(pass ? acc1[i] : acc0[i], lo, hi);
            r[2 + 2*i] = lo; r[3 + 2*i] = hi;
        }
        __syncthreads();
        for (int off = 4; off; off >>= 1) {
            if (j < off) {
                float* o = red + (t+off)*34;
                float mm = fmaxf(r[0], o[0]);
                float f1 = __expf(r[0]-mm), f2 = __expf(o[0]-mm);
                r[1] = r[1]*f1 + o[1]*f2;
                #pragma unroll
                for (int d = 0; d < 32; d++) r[2+d] = r[2+d]*f1 + o[2+d]*f2;
                r[0] = mm;
            }
            __syncthreads();
        }
        if (j == 0) {
            float inv = 1.f / r[1];
            float* op = out + ((size_t)b*N_ + qa + pass)*D_ + h*32;
            #pragma unroll
            for (int d = 0; d < 32; d++) op[d] = r[2+d]*inv;
        }
    }
}

// ---------------- decoder heads (warp per token) ----------------
__global__ void k_dec(const float* __restrict__ dWc, const float* __restrict__ dbc,
                      const float* __restrict__ dWf, const float* __restrict__ dbf) {
    int gid  = blockIdx.x*blockDim.x + threadIdx.x;
    int warp = gid >> 5;
    int lane = threadIdx.x & 31;
    if (warp >= B_*N_) return;
    int b = warp / N_, i = warp % N_;
    const float* tok = g_tokens + (size_t)warp*D_;
    bool isC = (i < NC_);
    const float* w = isC ? dWc : dWf;
    float a = 0.f;
    for (int d = lane; d < D_; d += 32) a += tok[d]*w[d];
    #pragma unroll
    for (int o = 16; o; o >>= 1) a += __shfl_xor_sync(~0u, a, o);
    if (lane == 0) {
        if (isC) g_c[b*NC_ + i] = a + dbc[0];
        else {
            int pos = i - NC_;
            float v = (pos < g_ntrue[b]) ? (a + dbf[0]) : 0.f;
            g_fmap[b*NF_ + g_order[b*NF_ + pos]] = v;
        }
    }
}

// bilinear (align_corners) upsample coarse 16->32; fine 32->32 is identity
__global__ void k_fuse() {
    int idx = blockIdx.x*blockDim.x + threadIdx.x;
    if (idx >= B_*OUT_*OUT_) return;
    int b = idx >> 10, oy = (idx >> 5) & 31, ox = idx & 31;
    float fy = oy * (15.f/31.f), fx = ox * (15.f/31.f);
    int y0 = (int)floorf(fy), x0 = (int)floorf(fx);
    int y1 = min(y0+1, 15), x1 = min(x0+1, 15);
    float wy = fy - y0, wx = fx - x0;
    const float* c = g_c + b*NC_;
    float cu = c[y0*16+x0]*(1.f-wy)*(1.f-wx) + c[y0*16+x1]*(1.f-wy)*wx
             + c[y1*16+x0]*wy*(1.f-wx)       + c[y1*16+x1]*wy*wx;
    g_fused[((b*2+0)*OUT_ + oy)*OUT_ + ox] = cu;
    g_fused[((b*2+1)*OUT_ + oy)*OUT_ + ox] = g_fmap[b*NF_ + oy*32 + ox];
}

__global__ void k_conv1(const float* __restrict__ w, const float* __restrict__ bias) {
    int idx = blockIdx.x*blockDim.x + threadIdx.x;
    if (idx >= B_*2*OUT_*OUT_) return;
    int ox = idx & 31, oy = (idx >> 5) & 31, co = (idx >> 10) & 1, b = idx >> 11;
    float a = bias[co];
    for (int ci = 0; ci < 2; ci++)
    for (int ky = 0; ky < 3; ky++)
    for (int kx = 0; kx < 3; kx++) {
        int y = oy + ky - 1, x2 = ox + kx - 1;
        if ((unsigned)y < 32u && (unsigned)x2 < 32u)
            a += g_fused[((b*2+ci)*OUT_ + y)*OUT_ + x2] * w[((co*2+ci)*3 + ky)*3 + kx];
    }
    g_hb[((b*2+co)*OUT_ + oy)*OUT_ + ox] = fmaxf(a, 0.f);
}

__global__ void k_conv2(const float* __restrict__ w, const float* __restrict__ bias,
                        float* __restrict__ out) {
    int idx = blockIdx.x*blockDim.x + threadIdx.x;
    if (idx >= B_*OUT_*OUT_) return;
    int ox = idx & 31, oy = (idx >> 5) & 31, b = idx >> 10;
    float a = bias[0];
    for (int ci = 0; ci < 2; ci++)
    for (int ky = 0; ky < 3; ky++)
    for (int kx = 0; kx < 3; kx++) {
        int y = oy + ky - 1, x2 = ox + kx - 1;
        if ((unsigned)y < 32u && (unsigned)x2 < 32u)
            a += g_hb[((b*2+ci)*OUT_ + y)*OUT_ + x2] * w[(ci*3 + ky)*3 + kx];
    }
    out[b*OUT_*OUT_ + oy*OUT_ + ox] = a;
}

// ---------------- host orchestration ----------------
extern "C" void kernel_launch(void* const* d_in, const int* in_sizes, int n_in,
                              void* d_out, int out_size) {
    const float* x    = (const float*)d_in[0];
    const float* Wpc  = (const float*)d_in[1];
    const float* bpc  = (const float*)d_in[2];
    const float* Wpf  = (const float*)d_in[3];
    const float* bpf  = (const float*)d_in[4];
    const float* te   = (const float*)d_in[5];
    const float* ln1g = (const float*)d_in[6];
    const float* ln1b = (const float*)d_in[7];
    const float* Wqkv = (const float*)d_in[8];
    const float* Wo   = (const float*)d_in[9];
    const float* bo   = (const float*)d_in[10];
    const float* ln2g = (const float*)d_in[11];
    const float* ln2b = (const float*)d_in[12];
    const float* W1   = (const float*)d_in[13];
    const float* b1   = (const float*)d_in[14];
    const float* W2   = (const float*)d_in[15];
    const float* b2   = (const float*)d_in[16];
    const float* dWc  = (const float*)d_in[17];
    const float* dbc  = (const float*)d_in[18];
    const float* dWf  = (const float*)d_in[19];
    const float* dbf  = (const float*)d_in[20];
    const float* fW1  = (const float*)d_in[21];
    const float* fb1  = (const float*)d_in[22];
    const float* fW2  = (const float*)d_in[23];
    const float* fb2  = (const float*)d_in[24];
    float* out = (float*)d_out;

    float *p_tokens, *p_y, *p_qkv, *p_att, *p_h1;
    cudaGetSymbolAddress((void**)&p_tokens, g_tokens);
    cudaGetSymbolAddress((void**)&p_y,      g_y);
    cudaGetSymbolAddress((void**)&p_qkv,    g_qkv);
    cudaGetSymbolAddress((void**)&p_att,    g_att);
    cudaGetSymbolAddress((void**)&p_h1,     g_h1);

    const int M = B_ * N_; // 10240

    k_coarse  <<<B_*NC_, 128>>>(x, Wpc, bpc, te);
    k_fine    <<<B_*NF_, 128>>>(x, Wpf, bpf);
    k_edge    <<<(B_*NF_ + 255)/256, 256>>>(x);
    k_mask    <<<B_, 256>>>();
    k_order   <<<B_, 1024>>>();
    k_assemble<<<B_*NF_, 128>>>(te);

    for (int l = 0; l < L_; l++) {
        k_ln<<<M, 128>>>(p_tokens, ln1g + l*D_, ln1b + l*D_, p_y);
        sgemm<<<dim3(384/64, M/64), 256>>>(p_y, Wqkv + (size_t)l*D_*3*D_,
                                           nullptr, nullptr, p_qkv, M, 384, 128, 0);
        k_attn<<<dim3(N_/32, H_, B_), 128>>>(p_qkv, p_att);
        sgemm<<<dim3(128/64, M/64), 256>>>(p_att, Wo + (size_t)l*D_*D_,
                                           bo + l*D_, p_tokens, p_tokens, M, 128, 128, 0);
        k_ln<<<M, 128>>>(p_tokens, ln2g + l*D_, ln2b + l*D_, p_y);
        sgemm<<<dim3(256/64, M/64), 256>>>(p_y, W1 + (size_t)l*D_*2*D_,
                                           b1 + l*2*D_, nullptr, p_h1, M, 256, 128, 1);
        sgemm<<<dim3(128/64, M/64), 256>>>(p_h1, W2 + (size_t)l*2*D_*D_,
                                           b2 + l*D_, p_tokens, p_tokens, M, 128, 256, 0);
    }

    k_dec  <<<(B_*N_*32 + 255)/256, 256>>>(dWc, dbc, dWf, dbf);
    k_fuse <<<(B_*OUT_*OUT_ + 255)/256, 256>>>();
    k_conv1<<<(B_*2*OUT_*OUT_ + 255)/256, 256>>>(fW1, fb1);
    k_conv2<<<(B_*OUT_*OUT_ + 255)/256, 256>>>(fW2, fb2, out);
}

// round 5
// speedup vs baseline: 2.8974x; 2.8974x over previous
#include <cuda_runtime.h>
#include <math.h>

// ---------------- problem constants ----------------
namespace {
constexpr int B_   = 8;
constexpr int IMG_ = 128;
constexpr int D_   = 128;
constexpr int H_   = 4;
constexpr int HD_  = 32;
constexpr int L_   = 2;
constexpr int NC_  = 256;   // 16x16 coarse tokens
constexpr int NF_  = 1024;  // 32x32 fine tokens
constexpr int N_   = 1280;  // NC+NF
constexpr int OUT_ = 32;
constexpr float SCALE_ = 0.17677669529663687f; // 32^-0.5
}

// ---------------- scratch (static device globals; no allocations) ----------------
// NOTE: zero-initialized at module load. Rows skipped by the pad-dedup logic are
// never written and never read with nonzero weight, so they stay finite forever.
__device__ float g_fine  [B_*NF_*D_];
__device__ float g_tokens[B_*N_*D_];
__device__ float g_y     [B_*N_*D_];
__device__ float g_qkv   [B_*N_*3*D_];
__device__ float g_att   [B_*N_*D_];
__device__ float g_h1    [B_*N_*2*D_];
__device__ float g_e     [B_*NF_];
__device__ int   g_mask  [B_*NF_];
__device__ int   g_order [B_*NF_];
__device__ int   g_ntrue [B_];
__device__ float g_c     [B_*NC_];
__device__ float g_fmap  [B_*NF_];
__device__ float g_fused [B_*2*OUT_*OUT_];
__device__ float g_hb    [B_*2*OUT_*OUT_];

// ---------------- patch embeds ----------------
__global__ void k_coarse(const float* __restrict__ x, const float* __restrict__ Wpc,
                         const float* __restrict__ bpc, const float* __restrict__ te) {
    __shared__ float sp[64];
    int blk = blockIdx.x;
    int b = blk >> 8, tok = blk & 255;
    int i = tok >> 4, j = tok & 15;
    int t = threadIdx.x;
    if (t < 64) {
        int pr = t >> 3, pc = t & 7;
        sp[t] = x[(b*IMG_ + i*8 + pr)*IMG_ + j*8 + pc];
    }
    __syncthreads();
    float acc = 0.f;
    #pragma unroll
    for (int p = 0; p < 64; p++) acc += sp[p] * Wpc[p*D_ + t];
    g_tokens[((size_t)b*N_ + tok)*D_ + t] = acc + bpc[t] + te[t];
}

__global__ void k_fine(const float* __restrict__ x, const float* __restrict__ Wpf,
                       const float* __restrict__ bpf) {
    __shared__ float sp[16];
    int blk = blockIdx.x;
    int b = blk >> 10, tok = blk & 1023;
    int i = tok >> 5, j = tok & 31;
    int t = threadIdx.x;
    if (t < 16) {
        int pr = t >> 2, pc = t & 3;
        sp[t] = x[(b*IMG_ + i*4 + pr)*IMG_ + j*4 + pc];
    }
    __syncthreads();
    float acc = 0.f;
    #pragma unroll
    for (int p = 0; p < 16; p++) acc += sp[p] * Wpf[p*D_ + t];
    g_fine[((size_t)b*NF_ + tok)*D_ + t] = acc + bpf[t];
}

// ---------------- edge map: sobel -> 4x4 avgpool ----------------
__device__ __forceinline__ float xat(const float* x, int b, int y, int c) {
    if ((unsigned)y >= (unsigned)IMG_ || (unsigned)c >= (unsigned)IMG_) return 0.f;
    return x[(b*IMG_ + y)*IMG_ + c];
}

__global__ void k_edge(const float* __restrict__ x) {
    int idx = blockIdx.x*blockDim.x + threadIdx.x;
    if (idx >= B_*NF_) return;
    int b = idx >> 10, cell = idx & 1023;
    int yi = cell >> 5, xi = cell & 31;
    float acc = 0.f;
    for (int dy = 0; dy < 4; dy++)
    for (int dx = 0; dx < 4; dx++) {
        int py = yi*4 + dy, px = xi*4 + dx;
        float a  = xat(x,b,py-1,px-1), bv = xat(x,b,py-1,px), c  = xat(x,b,py-1,px+1);
        float d  = xat(x,b,py  ,px-1),                         e2 = xat(x,b,py  ,px+1);
        float f  = xat(x,b,py+1,px-1), g  = xat(x,b,py+1,px), h2 = xat(x,b,py+1,px+1);
        float gx = -a + c - 2.f*d + 2.f*e2 - f + h2;
        float gy = -a - 2.f*bv - c + f + 2.f*g + h2;
        acc += sqrtf(gx*gx + gy*gy);
    }
    g_e[idx] = acc * (1.f/16.f);
}

__global__ void k_mask() {
    int b = blockIdx.x, t = threadIdx.x;   // 256 threads
    __shared__ float sh[256];
    float s = 0.f;
    for (int i = t; i < NF_; i += 256) s += g_e[b*NF_ + i];
    sh[t] = s; __syncthreads();
    for (int o = 128; o; o >>= 1) { if (t < o) sh[t] += sh[t+o]; __syncthreads(); }
    float mean = sh[0] * (1.f/NF_);
    for (int i = t; i < NF_; i += 256)
        g_mask[b*NF_ + i] = (g_e[b*NF_ + i] > mean) ? 1 : 0;
}

// stable argsort of !mask via prefix sum: edge tokens first, pixel order preserved
__global__ void k_order() {
    int b = blockIdx.x, t = threadIdx.x;   // 1024 threads
    __shared__ int sh[1024];
    int m = g_mask[b*NF_ + t];
    sh[t] = m; __syncthreads();
    for (int o = 1; o < 1024; o <<= 1) {
        int v = (t >= o) ? sh[t-o] : 0;
        __syncthreads();
        sh[t] += v;
        __syncthreads();
    }
    int incl = sh[t];
    int total = sh[1023];
    int pos = m ? (incl - 1) : (total + t - incl);
    g_order[b*NF_ + pos] = t;
    if (t == 0) g_ntrue[b] = total;
}

__global__ void k_assemble(const float* __restrict__ te) {
    int blk = blockIdx.x;
    int b = blk >> 10, pos = blk & 1023;
    int t = threadIdx.x;
    float v = te[D_ + t];
    if (pos < g_ntrue[b])
        v += g_fine[((size_t)b*NF_ + g_order[b*NF_ + pos])*D_ + t];
    g_tokens[((size_t)b*N_ + NC_ + pos)*D_ + t] = v;
}

// ---------------- layernorm (one block per token row, D=128) ----------------
// Skips rows strictly beyond the representative pad row (their outputs are
// never observed). Skipped g_y rows remain zero from static init.
__global__ void k_ln(const float* __restrict__ in, const float* __restrict__ g,
                     const float* __restrict__ bb, float* __restrict__ out) {
    int row = blockIdx.x, t = threadIdx.x;
    int b = row / N_;
    if (row - b*N_ > NC_ + g_ntrue[b]) return;   // pad row beyond representative
    float v = in[(size_t)row*D_ + t];
    float s = v, q = v*v;
    #pragma unroll
    for (int o = 16; o; o >>= 1) {
        s += __shfl_xor_sync(~0u, s, o);
        q += __shfl_xor_sync(~0u, q, o);
    }
    __shared__ float ss[4], sq[4];
    int w = t >> 5, lane = t & 31;
    if (lane == 0) { ss[w] = s; sq[w] = q; }
    __syncthreads();
    s = ss[0]+ss[1]+ss[2]+ss[3];
    q = sq[0]+sq[1]+sq[2]+sq[3];
    float mean = s * (1.f/D_);
    float var  = q * (1.f/D_) - mean*mean;
    out[(size_t)row*D_ + t] = (v - mean) * rsqrtf(var + 1e-5f) * g[t] + bb[t];
}

// ---------------- SGEMM: C = act(A@W + bias) + res ----------------
// 128x64 block tile, BK=16, 256 threads, 8x4 micro-tile.
// Tiles whose rows all lie beyond the per-batch representative pad row are skipped
// (those rows are never observed downstream). M rows are token rows: M = B*N_.
__global__ __launch_bounds__(256) void sgemm(
    const float* __restrict__ A, const float* __restrict__ Bw,
    const float* __restrict__ bias, const float* __restrict__ res,
    float* __restrict__ C, int M, int Nn, int K, int act)
{
    int m0 = blockIdx.y*128, n0 = blockIdx.x*64;
    {   // pad-dedup skip: all 128 rows beyond the representative -> dead tile
        int bb = m0 / N_;
        if (m0 - bb*N_ > NC_ + g_ntrue[bb]) return;
    }
    __shared__ __align__(16) float As[16][132];   // padded stride: store conflicts 4->2 way
    __shared__ __align__(16) float Bs[16][64];
    int t = threadIdx.x;
    int ty = t >> 4, tx = t & 15;     // ty: 8-row group (0..15), tx: 4-col group (0..15)
    float acc[8][4] = {};
    for (int k0 = 0; k0 < K; k0 += 16) {
        #pragma unroll
        for (int r = 0; r < 2; r++) {
            int idx = (t + r*256)*4;
            int ar = idx >> 4, ac = idx & 15;
            float4 v = *(const float4*)(A + (size_t)(m0+ar)*K + k0 + ac);
            As[ac  ][ar] = v.x; As[ac+1][ar] = v.y;
            As[ac+2][ar] = v.z; As[ac+3][ar] = v.w;
        }
        {
            int idx = t*4;
            int br = idx >> 6, bc = idx & 63;
            float4 v = *(const float4*)(Bw + (size_t)(k0+br)*Nn + n0 + bc);
            *(float4*)&Bs[br][bc] = v;
        }
        __syncthreads();
        #pragma unroll
        for (int kk = 0; kk < 16; kk++) {
            float4 a0 = *(const float4*)&As[kk][ty*8];
            float4 a1 = *(const float4*)&As[kk][ty*8+4];
            float4 bv = *(const float4*)&Bs[kk][tx*4];
            float av[8] = {a0.x,a0.y,a0.z,a0.w,a1.x,a1.y,a1.z,a1.w};
            float bb4[4] = {bv.x,bv.y,bv.z,bv.w};
            #pragma unroll
            for (int i = 0; i < 8; i++)
                #pragma unroll
                for (int jj = 0; jj < 4; jj++)
                    acc[i][jj] += av[i] * bb4[jj];
        }
        __syncthreads();
    }
    #pragma unroll
    for (int i = 0; i < 8; i++) {
        int m = m0 + ty*8 + i;
        int n = n0 + tx*4;
        float4 v = make_float4(acc[i][0], acc[i][1], acc[i][2], acc[i][3]);
        if (bias) {
            v.x += bias[n]; v.y += bias[n+1]; v.z += bias[n+2]; v.w += bias[n+3];
        }
        if (act == 1) {
            v.x = 0.5f*v.x*(1.f + erff(v.x*0.70710678118654752f));
            v.y = 0.5f*v.y*(1.f + erff(v.y*0.70710678118654752f));
            v.z = 0.5f*v.z*(1.f + erff(v.z*0.70710678118654752f));
            v.w = 0.5f*v.w*(1.f + erff(v.w*0.70710678118654752f));
        }
        if (res) {
            float4 rv = *(const float4*)(res + (size_t)m*Nn + n);
            v.x += rv.x; v.y += rv.y; v.z += rv.z; v.w += rv.w;
        }
        *(float4*)(C + (size_t)m*Nn + n) = v;
    }
}

// ---------------- attention: online softmax with pad dedup ----------------
// All pad tokens per batch are identical -> one representative key with
// multiplicity npad; query blocks entirely beyond the representative exit.
// 32 q / block, 2 q / thread, 8-way key split.
__global__ __launch_bounds__(128) void k_attn(const float* __restrict__ qkv,
                                              float* __restrict__ out) {
    __shared__ float Ks[64][36];
    __shared__ float Vs[64][36];
    __shared__ float red[128*34];
    int b = blockIdx.z, h = blockIdx.y, q0 = blockIdx.x*32;
    int ntrue = g_ntrue[b];
    int rep = NC_ + ntrue;                 // representative pad row (== N_ if no pads)
    if (q0 > rep) return;                  // whole block is dead pad queries
    float wpad = (float)(NF_ - ntrue);     // multiplicity of representative key
    int nkv = (rep < N_) ? (rep + 1) : N_; // distinct keys incl. representative
    int t = threadIdx.x;
    int j = t & 7, qp = t >> 3;
    int qa = q0 + qp*2;

    const float* qptr = qkv + ((size_t)b*N_ + qa)*384 + h*32;
    float qra[32], qrb[32];
    #pragma unroll
    for (int d = 0; d < 32; d++) { qra[d] = qptr[d]*SCALE_; qrb[d] = qptr[384+d]*SCALE_; }

    float m0 = -1e30f, s0 = 0.f, m1 = -1e30f, s1 = 0.f;
    float acc0[32], acc1[32];
    #pragma unroll
    for (int d = 0; d < 32; d++) { acc0[d] = 0.f; acc1[d] = 0.f; }

    for (int k0 = 0; k0 < nkv; k0 += 64) {
        __syncthreads();
        for (int i = t; i < 512; i += 128) {
            int key = i >> 3, dq = (i & 7) << 2;
            const float* kp = qkv + ((size_t)b*N_ + k0 + key)*384 + 128 + h*32 + dq;
            float4 kv = *(const float4*)kp;
            Ks[key][dq] = kv.x; Ks[key][dq+1] = kv.y; Ks[key][dq+2] = kv.z; Ks[key][dq+3] = kv.w;
            float4 vv = *(const float4*)(kp + 128);
            Vs[key][dq] = vv.x; Vs[key][dq+1] = vv.y; Vs[key][dq+2] = vv.z; Vs[key][dq+3] = vv.w;
        }
        __syncthreads();
        for (int kk = j; kk < 64; kk += 8) {
            int idx = k0 + kk;
            if (idx > rep) continue;                   // beyond distinct keys: weight 0
            float w = (idx == rep) ? wpad : 1.f;       // representative carries multiplicity
            float d0 = 0.f, d1 = 0.f;
            #pragma unroll
            for (int d = 0; d < 32; d += 4) {
                float4 kv = *(float4*)&Ks[kk][d];
                d0 += qra[d]*kv.x + qra[d+1]*kv.y + qra[d+2]*kv.z + qra[d+3]*kv.w;
                d1 += qrb[d]*kv.x + qrb[d+1]*kv.y + qrb[d+2]*kv.z + qrb[d+3]*kv.w;
            }
            if (d0 > m0) {
                float f = __expf(m0 - d0); s0 *= f;
                #pragma unroll
                for (int d = 0; d < 32; d++) acc0[d] *= f;
                m0 = d0;
            }
            float p0 = __expf(d0 - m0) * w; s0 += p0;
            if (d1 > m1) {
                float f = __expf(m1 - d1); s1 *= f;
                #pragma unroll
                for (int d = 0; d < 32; d++) acc1[d] *= f;
                m1 = d1;
            }
            float p1 = __expf(d1 - m1) * w; s1 += p1;
            #pragma unroll
            for (int d = 0; d < 32; d += 4) {
                float4 vv = *(float4*)&Vs[kk][d];
                acc0[d]   += p0*vv.x; acc0[d+1] += p0*vv.y;
                acc0[d+2] += p0*vv.z; acc0[d+3] += p0*vv.w;
                acc1[d]   += p1*vv.x; acc1[d+1] += p1*vv.y;
                acc1[d+2] += p1*vv.z; acc1[d+3] += p1*vv.w;
            }
        }
    }

    float* r = red + t*34;
    for (int pass = 0; pass < 2; pass++) {
        __syncthreads();
        r[0] = pass ? m1 : m0;
        r[1] = pass ? s1 : s0;
        #pragma unroll
        for (int d = 0; d < 32; d++) r[2+d] = pass ? acc1[d] : acc0[d];
        __syncthreads();
        for (int off = 4; off; off >>= 1) {
            if (j < off) {
                float* o = red + (t+off)*34;
                float mm = fmaxf(r[0], o[0]);
                float f1 = __expf(r[0]-mm), f2 = __expf(o[0]-mm);
                r[1] = r[1]*f1 + o[1]*f2;
                #pragma unroll
                for (int d = 0; d < 32; d++) r[2+d] = r[2+d]*f1 + o[2+d]*f2;
                r[0] = mm;
            }
            __syncthreads();
        }
        if (j == 0) {
            float inv = 1.f / r[1];
            float* op = out + ((size_t)b*N_ + qa + pass)*D_ + h*32;
            #pragma unroll
            for (int d = 0; d < 32; d++) op[d] = r[2+d]*inv;
        }
    }
}

// ---------------- decoder heads (warp per token) ----------------
__global__ void k_dec(const float* __restrict__ dWc, const float* __restrict__ dbc,
                      const float* __restrict__ dWf, const float* __restrict__ dbf) {
    int gid  = blockIdx.x*blockDim.x + threadIdx.x;
    int warp = gid >> 5;
    int lane = threadIdx.x & 31;
    if (warp >= B_*N_) return;
    int b = warp / N_, i = warp % N_;
    bool isC = (i < NC_);
    if (!isC && (i - NC_) >= g_ntrue[b]) {     // pad: feature is zero, skip dot
        if (lane == 0) g_fmap[b*NF_ + g_order[b*NF_ + (i - NC_)]] = 0.f;
        return;
    }
    const float* tok = g_tokens + (size_t)warp*D_;
    const float* w = isC ? dWc : dWf;
    float a = 0.f;
    for (int d = lane; d < D_; d += 32) a += tok[d]*w[d];
    #pragma unroll
    for (int o = 16; o; o >>= 1) a += __shfl_xor_sync(~0u, a, o);
    if (lane == 0) {
        if (isC) g_c[b*NC_ + i] = a + dbc[0];
        else     g_fmap[b*NF_ + g_order[b*NF_ + (i - NC_)]] = a + dbf[0];
    }
}

// bilinear (align_corners) upsample coarse 16->32; fine 32->32 is identity
__global__ void k_fuse() {
    int idx = blockIdx.x*blockDim.x + threadIdx.x;
    if (idx >= B_*OUT_*OUT_) return;
    int b = idx >> 10, oy = (idx >> 5) & 31, ox = idx & 31;
    float fy = oy * (15.f/31.f), fx = ox * (15.f/31.f);
    int y0 = (int)floorf(fy), x0 = (int)floorf(fx);
    int y1 = min(y0+1, 15), x1 = min(x0+1, 15);
    float wy = fy - y0, wx = fx - x0;
    const float* c = g_c + b*NC_;
    float cu = c[y0*16+x0]*(1.f-wy)*(1.f-wx) + c[y0*16+x1]*(1.f-wy)*wx
             + c[y1*16+x0]*wy*(1.f-wx)       + c[y1*16+x1]*wy*wx;
    g_fused[((b*2+0)*OUT_ + oy)*OUT_ + ox] = cu;
    g_fused[((b*2+1)*OUT_ + oy)*OUT_ + ox] = g_fmap[b*NF_ + oy*32 + ox];
}

__global__ void k_conv1(const float* __restrict__ w, const float* __restrict__ bias) {
    int idx = blockIdx.x*blockDim.x + threadIdx.x;
    if (idx >= B_*2*OUT_*OUT_) return;
    int ox = idx & 31, oy = (idx >> 5) & 31, co = (idx >> 10) & 1, b = idx >> 11;
    float a = bias[co];
    for (int ci = 0; ci < 2; ci++)
    for (int ky = 0; ky < 3; ky++)
    for (int kx = 0; kx < 3; kx++) {
        int y = oy + ky - 1, x2 = ox + kx - 1;
        if ((unsigned)y < 32u && (unsigned)x2 < 32u)
            a += g_fused[((b*2+ci)*OUT_ + y)*OUT_ + x2] * w[((co*2+ci)*3 + ky)*3 + kx];
    }
    g_hb[((b*2+co)*OUT_ + oy)*OUT_ + ox] = fmaxf(a, 0.f);
}

__global__ void k_conv2(const float* __restrict__ w, const float* __restrict__ bias,
                        float* __restrict__ out) {
    int idx = blockIdx.x*blockDim.x + threadIdx.x;
    if (idx >= B_*OUT_*OUT_) return;
    int ox = idx & 31, oy = (idx >> 5) & 31, b = idx >> 10;
    float a = bias[0];
    for (int ci = 0; ci < 2; ci++)
    for (int ky = 0; ky < 3; ky++)
    for (int kx = 0; kx < 3; kx++) {
        int y = oy + ky - 1, x2 = ox + kx - 1;
        if ((unsigned)y < 32u && (unsigned)x2 < 32u)
            a += g_hb[((b*2+ci)*OUT_ + y)*OUT_ + x2] * w[(ci*3 + ky)*3 + kx];
    }
    out[b*OUT_*OUT_ + oy*OUT_ + ox] = a;
}

// ---------------- host orchestration ----------------
extern "C" void kernel_launch(void* const* d_in, const int* in_sizes, int n_in,
                              void* d_out, int out_size) {
    const float* x    = (const float*)d_in[0];
    const float* Wpc  = (const float*)d_in[1];
    const float* bpc  = (const float*)d_in[2];
    const float* Wpf  = (const float*)d_in[3];
    const float* bpf  = (const float*)d_in[4];
    const float* te   = (const float*)d_in[5];
    const float* ln1g = (const float*)d_in[6];
    const float* ln1b = (const float*)d_in[7];
    const float* Wqkv = (const float*)d_in[8];
    const float* Wo   = (const float*)d_in[9];
    const float* bo   = (const float*)d_in[10];
    const float* ln2g = (const float*)d_in[11];
    const float* ln2b = (const float*)d_in[12];
    const float* W1   = (const float*)d_in[13];
    const float* b1   = (const float*)d_in[14];
    const float* W2   = (const float*)d_in[15];
    const float* b2   = (const float*)d_in[16];
    const float* dWc  = (const float*)d_in[17];
    const float* dbc  = (const float*)d_in[18];
    const float* dWf  = (const float*)d_in[19];
    const float* dbf  = (const float*)d_in[20];
    const float* fW1  = (const float*)d_in[21];
    const float* fb1  = (const float*)d_in[22];
    const float* fW2  = (const float*)d_in[23];
    const float* fb2  = (const float*)d_in[24];
    float* out = (float*)d_out;

    float *p_tokens, *p_y, *p_qkv, *p_att, *p_h1;
    cudaGetSymbolAddress((void**)&p_tokens, g_tokens);
    cudaGetSymbolAddress((void**)&p_y,      g_y);
    cudaGetSymbolAddress((void**)&p_qkv,    g_qkv);
    cudaGetSymbolAddress((void**)&p_att,    g_att);
    cudaGetSymbolAddress((void**)&p_h1,     g_h1);

    const int M = B_ * N_; // 10240

    k_coarse  <<<B_*NC_, 128>>>(x, Wpc, bpc, te);
    k_fine    <<<B_*NF_, 128>>>(x, Wpf, bpf);
    k_edge    <<<(B_*NF_ + 255)/256, 256>>>(x);
    k_mask    <<<B_, 256>>>();
    k_order   <<<B_, 1024>>>();
    k_assemble<<<B_*NF_, 128>>>(te);

    for (int l = 0; l < L_; l++) {
        k_ln<<<M, 128>>>(p_tokens, ln1g + l*D_, ln1b + l*D_, p_y);
        sgemm<<<dim3(384/64, M/128), 256>>>(p_y, Wqkv + (size_t)l*D_*3*D_,
                                            nullptr, nullptr, p_qkv, M, 384, 128, 0);
        k_attn<<<dim3(N_/32, H_, B_), 128>>>(p_qkv, p_att);
        sgemm<<<dim3(128/64, M/128), 256>>>(p_att, Wo + (size_t)l*D_*D_,
                                            bo + l*D_, p_tokens, p_tokens, M, 128, 128, 0);
        k_ln<<<M, 128>>>(p_tokens, ln2g + l*D_, ln2b + l*D_, p_y);
        sgemm<<<dim3(256/64, M/128), 256>>>(p_y, W1 + (size_t)l*D_*2*D_,
                                            b1 + l*2*D_, nullptr, p_h1, M, 256, 128, 1);
        sgemm<<<dim3(128/64, M/128), 256>>>(p_h1, W2 + (size_t)l*2*D_*D_,
                                            b2 + l*D_, p_tokens, p_tokens, M, 128, 256, 0);
    }

    k_dec  <<<(B_*N_*32 + 255)/256, 256>>>(dWc, dbc, dWf, dbf);
    k_fuse <<<(B_*OUT_*OUT_ + 255)/256, 256>>>();
    k_conv1<<<(B_*2*OUT_*OUT_ + 255)/256, 256>>>(fW1, fb1);
    k_conv2<<<(B_*OUT_*OUT_ + 255)/256, 256>>>(fW2, fb2, out);
}

// round 7
// speedup vs baseline: 3.0974x; 1.0690x over previous
#include <cuda_runtime.h>
#include <cuda_bf16.h>
#include <math.h>
#include <stdint.h>

// ---------------- problem constants ----------------
namespace {
constexpr int B_   = 8;
constexpr int IMG_ = 128;
constexpr int D_   = 128;
constexpr int H_   = 4;
constexpr int HD_  = 32;
constexpr int L_   = 2;
constexpr int NC_  = 256;   // 16x16 coarse tokens
constexpr int NF_  = 1024;  // 32x32 fine tokens
constexpr int N_   = 1280;  // NC+NF
constexpr int OUT_ = 32;
constexpr float SCALE_ = 0.17677669529663687f; // 32^-0.5
}

// ---------------- scratch (static device globals; no allocations) ----------------
__device__ float g_fine  [B_*NF_*D_];
__device__ float g_tokens[B_*N_*D_];
__device__ float g_y     [B_*N_*D_];
__device__ float g_qkv   [B_*N_*3*D_];
__device__ float g_att   [B_*N_*D_];
__device__ float g_h1    [B_*N_*2*D_];
__device__ float g_e     [B_*NF_];
__device__ int   g_mask  [B_*NF_];
__device__ int   g_order [B_*NF_];
__device__ int   g_ntrue [B_];
__device__ float g_c     [B_*NC_];
__device__ float g_fmap  [B_*NF_];
__device__ float g_fused [B_*2*OUT_*OUT_];
__device__ float g_hb    [B_*2*OUT_*OUT_];

// ---------------- patch embeds ----------------
__global__ void k_coarse(const float* __restrict__ x, const float* __restrict__ Wpc,
                         const float* __restrict__ bpc, const float* __restrict__ te) {
    __shared__ float sp[64];
    int blk = blockIdx.x;
    int b = blk >> 8, tok = blk & 255;
    int i = tok >> 4, j = tok & 15;
    int t = threadIdx.x;
    if (t < 64) {
        int pr = t >> 3, pc = t & 7;
        sp[t] = x[(b*IMG_ + i*8 + pr)*IMG_ + j*8 + pc];
    }
    __syncthreads();
    float acc = 0.f;
    #pragma unroll
    for (int p = 0; p < 64; p++) acc += sp[p] * Wpc[p*D_ + t];
    g_tokens[((size_t)b*N_ + tok)*D_ + t] = acc + bpc[t] + te[t];
}

__global__ void k_fine(const float* __restrict__ x, const float* __restrict__ Wpf,
                       const float* __restrict__ bpf) {
    __shared__ float sp[16];
    int blk = blockIdx.x;
    int b = blk >> 10, tok = blk & 1023;
    int i = tok >> 5, j = tok & 31;
    int t = threadIdx.x;
    if (t < 16) {
        int pr = t >> 2, pc = t & 3;
        sp[t] = x[(b*IMG_ + i*4 + pr)*IMG_ + j*4 + pc];
    }
    __syncthreads();
    float acc = 0.f;
    #pragma unroll
    for (int p = 0; p < 16; p++) acc += sp[p] * Wpf[p*D_ + t];
    g_fine[((size_t)b*NF_ + tok)*D_ + t] = acc + bpf[t];
}

// ---------------- edge map: sobel -> 4x4 avgpool ----------------
__device__ __forceinline__ float xat(const float* x, int b, int y, int c) {
    if ((unsigned)y >= (unsigned)IMG_ || (unsigned)c >= (unsigned)IMG_) return 0.f;
    return x[(b*IMG_ + y)*IMG_ + c];
}

__global__ void k_edge(const float* __restrict__ x) {
    int idx = blockIdx.x*blockDim.x + threadIdx.x;
    if (idx >= B_*NF_) return;
    int b = idx >> 10, cell = idx & 1023;
    int yi = cell >> 5, xi = cell & 31;
    float acc = 0.f;
    for (int dy = 0; dy < 4; dy++)
    for (int dx = 0; dx < 4; dx++) {
        int py = yi*4 + dy, px = xi*4 + dx;
        float a  = xat(x,b,py-1,px-1), bv = xat(x,b,py-1,px), c  = xat(x,b,py-1,px+1);
        float d  = xat(x,b,py  ,px-1),                         e2 = xat(x,b,py  ,px+1);
        float f  = xat(x,b,py+1,px-1), g  = xat(x,b,py+1,px), h2 = xat(x,b,py+1,px+1);
        float gx = -a + c - 2.f*d + 2.f*e2 - f + h2;
        float gy = -a - 2.f*bv - c + f + 2.f*g + h2;
        acc += sqrtf(gx*gx + gy*gy);
    }
    g_e[idx] = acc * (1.f/16.f);
}

__global__ void k_mask() {
    int b = blockIdx.x, t = threadIdx.x;   // 256 threads
    __shared__ float sh[256];
    float s = 0.f;
    for (int i = t; i < NF_; i += 256) s += g_e[b*NF_ + i];
    sh[t] = s; __syncthreads();
    for (int o = 128; o; o >>= 1) { if (t < o) sh[t] += sh[t+o]; __syncthreads(); }
    float mean = sh[0] * (1.f/NF_);
    for (int i = t; i < NF_; i += 256)
        g_mask[b*NF_ + i] = (g_e[b*NF_ + i] > mean) ? 1 : 0;
}

// stable argsort of !mask via prefix sum
__global__ void k_order() {
    int b = blockIdx.x, t = threadIdx.x;   // 1024 threads
    __shared__ int sh[1024];
    int m = g_mask[b*NF_ + t];
    sh[t] = m; __syncthreads();
    for (int o = 1; o < 1024; o <<= 1) {
        int v = (t >= o) ? sh[t-o] : 0;
        __syncthreads();
        sh[t] += v;
        __syncthreads();
    }
    int incl = sh[t];
    int total = sh[1023];
    int pos = m ? (incl - 1) : (total + t - incl);
    g_order[b*NF_ + pos] = t;
    if (t == 0) g_ntrue[b] = total;
}

__global__ void k_assemble(const float* __restrict__ te) {
    int blk = blockIdx.x;
    int b = blk >> 10, pos = blk & 1023;
    int t = threadIdx.x;
    float v = te[D_ + t];
    if (pos < g_ntrue[b])
        v += g_fine[((size_t)b*NF_ + g_order[b*NF_ + pos])*D_ + t];
    g_tokens[((size_t)b*N_ + NC_ + pos)*D_ + t] = v;
}

// ---------------- layernorm (one block per token row, D=128) ----------------
__global__ void k_ln(const float* __restrict__ in, const float* __restrict__ g,
                     const float* __restrict__ bb, float* __restrict__ out) {
    int row = blockIdx.x, t = threadIdx.x;
    int b = row / N_;
    if (row - b*N_ > NC_ + g_ntrue[b]) return;   // pad row beyond representative
    float v = in[(size_t)row*D_ + t];
    float s = v, q = v*v;
    #pragma unroll
    for (int o = 16; o; o >>= 1) {
        s += __shfl_xor_sync(~0u, s, o);
        q += __shfl_xor_sync(~0u, q, o);
    }
    __shared__ float ss[4], sq[4];
    int w = t >> 5, lane = t & 31;
    if (lane == 0) { ss[w] = s; sq[w] = q; }
    __syncthreads();
    s = ss[0]+ss[1]+ss[2]+ss[3];
    q = sq[0]+sq[1]+sq[2]+sq[3];
    float mean = s * (1.f/D_);
    float var  = q * (1.f/D_) - mean*mean;
    out[(size_t)row*D_ + t] = (v - mean) * rsqrtf(var + 1e-5f) * g[t] + bb[t];
}

// ---------------- tensor-core GEMM via mma.sync (bf16 hi/lo split) ----------------
// C = act(A@W + bias) + res.  Block tile 128x64, 256 threads (8 warps, 4x2 grid),
// warp tile 32x32 = 2 (m16) x 4 (n8) fragments, fp32 register accumulators.
// K consumed in chunks of 64. fp32 = hi + lo bf16; D += Ahi*Bhi + Ahi*Blo + Alo*Bhi.
// smem: u32 k-pair arrays, row stride 34 (2-way conflicts max):
//   Ahi[128][34] @0, Alo @17408, Bhi[64][34] @34816, Blo @43520  -> 52224 bytes
#define HG_SMEM 52224
__device__ __forceinline__ void mma16816(float* c, const uint32_t* a, const uint32_t* b) {
    asm volatile(
        "mma.sync.aligned.m16n8k16.row.col.f32.bf16.bf16.f32 "
        "{%0,%1,%2,%3}, {%4,%5,%6,%7}, {%8,%9}, {%0,%1,%2,%3};"
        : "+f"(c[0]), "+f"(c[1]), "+f"(c[2]), "+f"(c[3])
        : "r"(a[0]), "r"(a[1]), "r"(a[2]), "r"(a[3]), "r"(b[0]), "r"(b[1]));
}

__global__ __launch_bounds__(256) void hgemm(
    const float* __restrict__ A, const float* __restrict__ Bw,
    const float* __restrict__ bias, const float* __restrict__ res,
    float* __restrict__ C, int M, int Nn, int K, int act)
{
    int m0 = blockIdx.y*128, n0 = blockIdx.x*64;
    {   // pad-dedup: tiles entirely beyond the representative row are dead
        int bb = m0 / N_;
        if (m0 - bb*N_ > NC_ + g_ntrue[bb]) return;
    }
    extern __shared__ __align__(16) uint32_t sm[];
    uint32_t* Ahi = sm;                 // [128][34]
    uint32_t* Alo = sm + 4352;
    uint32_t* Bhi = sm + 8704;          // [64][34]
    uint32_t* Blo = sm + 10880;

    int t = threadIdx.x, wid = t >> 5, lane = t & 31;
    int wm = wid >> 1, wn = wid & 1;          // warp grid 4(M) x 2(N)
    int grp = lane >> 2, tig = lane & 3;

    float acc[2][4][4];
    #pragma unroll
    for (int i = 0; i < 2; i++)
        #pragma unroll
        for (int j = 0; j < 4; j++)
            #pragma unroll
            for (int q = 0; q < 4; q++) acc[i][j][q] = 0.f;

    int nchunk = K >> 6;
    for (int kc = 0; kc < nchunk; kc++) {
        // A: 128 rows x 32 k-pairs. Each thread: 16 pairs via float2 loads.
        #pragma unroll 4
        for (int it = 0; it < 16; it++) {
            int idx = it*256 + t;               // over 128x32 pairs
            int row = idx >> 5, p = idx & 31;
            float2 v = *(const float2*)(A + (size_t)(m0+row)*K + kc*64 + p*2);
            __nv_bfloat16 h0 = __float2bfloat16(v.x);
            __nv_bfloat16 l0 = __float2bfloat16(v.x - __bfloat162float(h0));
            __nv_bfloat16 h1 = __float2bfloat16(v.y);
            __nv_bfloat16 l1 = __float2bfloat16(v.y - __bfloat162float(h1));
            Ahi[row*34 + p] = (uint32_t)__bfloat16_as_ushort(h0) | ((uint32_t)__bfloat16_as_ushort(h1) << 16);
            Alo[row*34 + p] = (uint32_t)__bfloat16_as_ushort(l0) | ((uint32_t)__bfloat16_as_ushort(l1) << 16);
        }
        // B: W[k][n] -> Bsm[n][kpair] (mma col-major B). 64n x 32 pairs.
        #pragma unroll 4
        for (int it = 0; it < 8; it++) {
            int idx = it*256 + t;               // over 32 pairs x 64 n
            int p = idx >> 6, n = idx & 63;
            float v0 = Bw[(size_t)(kc*64 + p*2    )*Nn + n0 + n];
            float v1 = Bw[(size_t)(kc*64 + p*2 + 1)*Nn + n0 + n];
            __nv_bfloat16 h0 = __float2bfloat16(v0);
            __nv_bfloat16 l0 = __float2bfloat16(v0 - __bfloat162float(h0));
            __nv_bfloat16 h1 = __float2bfloat16(v1);
            __nv_bfloat16 l1 = __float2bfloat16(v1 - __bfloat162float(h1));
            Bhi[n*34 + p] = (uint32_t)__bfloat16_as_ushort(h0) | ((uint32_t)__bfloat16_as_ushort(h1) << 16);
            Blo[n*34 + p] = (uint32_t)__bfloat16_as_ushort(l0) | ((uint32_t)__bfloat16_as_ushort(l1) << 16);
        }
        __syncthreads();

        #pragma unroll
        for (int s = 0; s < 4; s++) {           // 4 x k16 steps per 64-chunk
            int pb = s*8;
            // load fragments
            uint32_t ah[2][4], al[2][4], bh[4][2], bl[4][2];
            #pragma unroll
            for (int mt = 0; mt < 2; mt++) {
                int r = (wm*32 + mt*16 + grp)*34;
                ah[mt][0] = Ahi[r + pb + tig];          al[mt][0] = Alo[r + pb + tig];
                ah[mt][1] = Ahi[r + 8*34 + pb + tig];   al[mt][1] = Alo[r + 8*34 + pb + tig];
                ah[mt][2] = Ahi[r + pb + 4 + tig];      al[mt][2] = Alo[r + pb + 4 + tig];
                ah[mt][3] = Ahi[r + 8*34 + pb + 4 + tig]; al[mt][3] = Alo[r + 8*34 + pb + 4 + tig];
            }
            #pragma unroll
            for (int nt = 0; nt < 4; nt++) {
                int r = (wn*32 + nt*8 + grp)*34;
                bh[nt][0] = Bhi[r + pb + tig];     bl[nt][0] = Blo[r + pb + tig];
                bh[nt][1] = Bhi[r + pb + 4 + tig]; bl[nt][1] = Blo[r + pb + 4 + tig];
            }
            #pragma unroll
            for (int mt = 0; mt < 2; mt++)
                #pragma unroll
                for (int nt = 0; nt < 4; nt++) {
                    mma16816(acc[mt][nt], ah[mt], bh[nt]);
                    mma16816(acc[mt][nt], ah[mt], bl[nt]);
                    mma16816(acc[mt][nt], al[mt], bh[nt]);
                }
        }
        __syncthreads();
    }

    // epilogue: c0,c1 -> (row grp, cols tig*2..+1); c2,c3 -> row grp+8
    #pragma unroll
    for (int mt = 0; mt < 2; mt++) {
        #pragma unroll
        for (int nt = 0; nt < 4; nt++) {
            int col = n0 + wn*32 + nt*8 + tig*2;
            #pragma unroll
            for (int half = 0; half < 2; half++) {
                int row = m0 + wm*32 + mt*16 + grp + half*8;
                float v0 = acc[mt][nt][half*2], v1 = acc[mt][nt][half*2+1];
                if (bias) { v0 += bias[col]; v1 += bias[col+1]; }
                if (act == 1) {
                    v0 = 0.5f*v0*(1.f + erff(v0*0.70710678118654752f));
                    v1 = 0.5f*v1*(1.f + erff(v1*0.70710678118654752f));
                }
                if (res) {
                    float2 rv = *(const float2*)(res + (size_t)row*Nn + col);
                    v0 += rv.x; v1 += rv.y;
                }
                *(float2*)(C + (size_t)row*Nn + col) = make_float2(v0, v1);
            }
        }
    }
}

// ---------------- attention: online softmax with pad dedup (scalar fp32) ----------------
__global__ __launch_bounds__(128) void k_attn(const float* __restrict__ qkv,
                                              float* __restrict__ out) {
    __shared__ float Ks[64][36];
    __shared__ float Vs[64][36];
    __shared__ float red[128*34];
    int b = blockIdx.z, h = blockIdx.y, q0 = blockIdx.x*32;
    int ntrue = g_ntrue[b];
    int rep = NC_ + ntrue;
    if (q0 > rep) return;
    float wpad = (float)(NF_ - ntrue);
    int nkv = (rep < N_) ? (rep + 1) : N_;
    int t = threadIdx.x;
    int j = t & 7, qp = t >> 3;
    int qa = q0 + qp*2;

    const float* qptr = qkv + ((size_t)b*N_ + qa)*384 + h*32;
    float qra[32], qrb[32];
    #pragma unroll
    for (int d = 0; d < 32; d++) { qra[d] = qptr[d]*SCALE_; qrb[d] = qptr[384+d]*SCALE_; }

    float m0 = -1e30f, s0 = 0.f, m1 = -1e30f, s1 = 0.f;
    float acc0[32], acc1[32];
    #pragma unroll
    for (int d = 0; d < 32; d++) { acc0[d] = 0.f; acc1[d] = 0.f; }

    for (int k0 = 0; k0 < nkv; k0 += 64) {
        __syncthreads();
        for (int i = t; i < 512; i += 128) {
            int key = i >> 3, dq = (i & 7) << 2;
            const float* kp = qkv + ((size_t)b*N_ + k0 + key)*384 + 128 + h*32 + dq;
            float4 kv = *(const float4*)kp;
            Ks[key][dq] = kv.x; Ks[key][dq+1] = kv.y; Ks[key][dq+2] = kv.z; Ks[key][dq+3] = kv.w;
            float4 vv = *(const float4*)(kp + 128);
            Vs[key][dq] = vv.x; Vs[key][dq+1] = vv.y; Vs[key][dq+2] = vv.z; Vs[key][dq+3] = vv.w;
        }
        __syncthreads();
        for (int kk = j; kk < 64; kk += 8) {
            int idx = k0 + kk;
            if (idx > rep) continue;
            float w = (idx == rep) ? wpad : 1.f;
            float d0 = 0.f, d1 = 0.f;
            #pragma unroll
            for (int d = 0; d < 32; d += 4) {
                float4 kv = *(float4*)&Ks[kk][d];
                d0 += qra[d]*kv.x + qra[d+1]*kv.y + qra[d+2]*kv.z + qra[d+3]*kv.w;
                d1 += qrb[d]*kv.x + qrb[d+1]*kv.y + qrb[d+2]*kv.z + qrb[d+3]*kv.w;
            }
            if (d0 > m0) {
                float f = __expf(m0 - d0); s0 *= f;
                #pragma unroll
                for (int d = 0; d < 32; d++) acc0[d] *= f;
                m0 = d0;
            }
            float p0 = __expf(d0 - m0) * w; s0 += p0;
            if (d1 > m1) {
                float f = __expf(m1 - d1); s1 *= f;
                #pragma unroll
                for (int d = 0; d < 32; d++) acc1[d] *= f;
                m1 = d1;
            }
            float p1 = __expf(d1 - m1) * w; s1 += p1;
            #pragma unroll
            for (int d = 0; d < 32; d += 4) {
                float4 vv = *(float4*)&Vs[kk][d];
                acc0[d]   += p0*vv.x; acc0[d+1] += p0*vv.y;
                acc0[d+2] += p0*vv.z; acc0[d+3] += p0*vv.w;
                acc1[d]   += p1*vv.x; acc1[d+1] += p1*vv.y;
                acc1[d+2] += p1*vv.z; acc1[d+3] += p1*vv.w;
            }
        }
    }

    float* r = red + t*34;
    for (int pass = 0; pass < 2; pass++) {
        __syncthreads();
        r[0] = pass ? m1 : m0;
        r[1] = pass ? s1 : s0;
        #pragma unroll
        for (int d = 0; d < 32; d++) r[2+d] = pass ? acc1[d] : acc0[d];
        __syncthreads();
        for (int off = 4; off; off >>= 1) {
            if (j < off) {
                float* o = red + (t+off)*34;
                float mm = fmaxf(r[0], o[0]);
                float f1 = __expf(r[0]-mm), f2 = __expf(o[0]-mm);
                r[1] = r[1]*f1 + o[1]*f2;
                #pragma unroll
                for (int d = 0; d < 32; d++) r[2+d] = r[2+d]*f1 + o[2+d]*f2;
                r[0] = mm;
            }
            __syncthreads();
        }
        if (j == 0) {
            float inv = 1.f / r[1];
            float* op = out + ((size_t)b*N_ + qa + pass)*D_ + h*32;
            #pragma unroll
            for (int d = 0; d < 32; d++) op[d] = r[2+d]*inv;
        }
    }
}

// ---------------- decoder heads (warp per token) ----------------
__global__ void k_dec(const float* __restrict__ dWc, const float* __restrict__ dbc,
                      const float* __restrict__ dWf, const float* __restrict__ dbf) {
    int gid  = blockIdx.x*blockDim.x + threadIdx.x;
    int warp = gid >> 5;
    int lane = threadIdx.x & 31;
    if (warp >= B_*N_) return;
    int b = warp / N_, i = warp % N_;
    bool isC = (i < NC_);
    if (!isC && (i - NC_) >= g_ntrue[b]) {
        if (lane == 0) g_fmap[b*NF_ + g_order[b*NF_ + (i - NC_)]] = 0.f;
        return;
    }
    const float* tok = g_tokens + (size_t)warp*D_;
    const float* w = isC ? dWc : dWf;
    float a = 0.f;
    for (int d = lane; d < D_; d += 32) a += tok[d]*w[d];
    #pragma unroll
    for (int o = 16; o; o >>= 1) a += __shfl_xor_sync(~0u, a, o);
    if (lane == 0) {
        if (isC) g_c[b*NC_ + i] = a + dbc[0];
        else     g_fmap[b*NF_ + g_order[b*NF_ + (i - NC_)]] = a + dbf[0];
    }
}

// bilinear (align_corners) upsample coarse 16->32; fine 32->32 is identity
__global__ void k_fuse() {
    int idx = blockIdx.x*blockDim.x + threadIdx.x;
    if (idx >= B_*OUT_*OUT_) return;
    int b = idx >> 10, oy = (idx >> 5) & 31, ox = idx & 31;
    float fy = oy * (15.f/31.f), fx = ox * (15.f/31.f);
    int y0 = (int)floorf(fy), x0 = (int)floorf(fx);
    int y1 = min(y0+1, 15), x1 = min(x0+1, 15);
    float wy = fy - y0, wx = fx - x0;
    const float* c = g_c + b*NC_;
    float cu = c[y0*16+x0]*(1.f-wy)*(1.f-wx) + c[y0*16+x1]*(1.f-wy)*wx
             + c[y1*16+x0]*wy*(1.f-wx)       + c[y1*16+x1]*wy*wx;
    g_fused[((b*2+0)*OUT_ + oy)*OUT_ + ox] = cu;
    g_fused[((b*2+1)*OUT_ + oy)*OUT_ + ox] = g_fmap[b*NF_ + oy*32 + ox];
}

__global__ void k_conv1(const float* __restrict__ w, const float* __restrict__ bias) {
    int idx = blockIdx.x*blockDim.x + threadIdx.x;
    if (idx >= B_*2*OUT_*OUT_) return;
    int ox = idx & 31, oy = (idx >> 5) & 31, co = (idx >> 10) & 1, b = idx >> 11;
    float a = bias[co];
    for (int ci = 0; ci < 2; ci++)
    for (int ky = 0; ky < 3; ky++)
    for (int kx = 0; kx < 3; kx++) {
        int y = oy + ky - 1, x2 = ox + kx - 1;
        if ((unsigned)y < 32u && (unsigned)x2 < 32u)
            a += g_fused[((b*2+ci)*OUT_ + y)*OUT_ + x2] * w[((co*2+ci)*3 + ky)*3 + kx];
    }
    g_hb[((b*2+co)*OUT_ + oy)*OUT_ + ox] = fmaxf(a, 0.f);
}

__global__ void k_conv2(const float* __restrict__ w, const float* __restrict__ bias,
                        float* __restrict__ out) {
    int idx = blockIdx.x*blockDim.x + threadIdx.x;
    if (idx >= B_*OUT_*OUT_) return;
    int ox = idx & 31, oy = (idx >> 5) & 31, b = idx >> 10;
    float a = bias[0];
    for (int ci = 0; ci < 2; ci++)
    for (int ky = 0; ky < 3; ky++)
    for (int kx = 0; kx < 3; kx++) {
        int y = oy + ky - 1, x2 = ox + kx - 1;
        if ((unsigned)y < 32u && (unsigned)x2 < 32u)
            a += g_hb[((b*2+ci)*OUT_ + y)*OUT_ + x2] * w[(ci*3 + ky)*3 + kx];
    }
    out[b*OUT_*OUT_ + oy*OUT_ + ox] = a;
}

// ---------------- host orchestration ----------------
extern "C" void kernel_launch(void* const* d_in, const int* in_sizes, int n_in,
                              void* d_out, int out_size) {
    const float* x    = (const float*)d_in[0];
    const float* Wpc  = (const float*)d_in[1];
    const float* bpc  = (const float*)d_in[2];
    const float* Wpf  = (const float*)d_in[3];
    const float* bpf  = (const float*)d_in[4];
    const float* te   = (const float*)d_in[5];
    const float* ln1g = (const float*)d_in[6];
    const float* ln1b = (const float*)d_in[7];
    const float* Wqkv = (const float*)d_in[8];
    const float* Wo   = (const float*)d_in[9];
    const float* bo   = (const float*)d_in[10];
    const float* ln2g = (const float*)d_in[11];
    const float* ln2b = (const float*)d_in[12];
    const float* W1   = (const float*)d_in[13];
    const float* b1   = (const float*)d_in[14];
    const float* W2   = (const float*)d_in[15];
    const float* b2   = (const float*)d_in[16];
    const float* dWc  = (const float*)d_in[17];
    const float* dbc  = (const float*)d_in[18];
    const float* dWf  = (const float*)d_in[19];
    const float* dbf  = (const float*)d_in[20];
    const float* fW1  = (const float*)d_in[21];
    const float* fb1  = (const float*)d_in[22];
    const float* fW2  = (const float*)d_in[23];
    const float* fb2  = (const float*)d_in[24];
    float* out = (float*)d_out;

    float *p_tokens, *p_y, *p_qkv, *p_att, *p_h1;
    cudaGetSymbolAddress((void**)&p_tokens, g_tokens);
    cudaGetSymbolAddress((void**)&p_y,      g_y);
    cudaGetSymbolAddress((void**)&p_qkv,    g_qkv);
    cudaGetSymbolAddress((void**)&p_att,    g_att);
    cudaGetSymbolAddress((void**)&p_h1,     g_h1);

    cudaFuncSetAttribute(hgemm, cudaFuncAttributeMaxDynamicSharedMemorySize, HG_SMEM);

    const int M = B_ * N_; // 10240

    k_coarse  <<<B_*NC_, 128>>>(x, Wpc, bpc, te);
    k_fine    <<<B_*NF_, 128>>>(x, Wpf, bpf);
    k_edge    <<<(B_*NF_ + 255)/256, 256>>>(x);
    k_mask    <<<B_, 256>>>();
    k_order   <<<B_, 1024>>>();
    k_assemble<<<B_*NF_, 128>>>(te);

    for (int l = 0; l < L_; l++) {
        k_ln<<<M, 128>>>(p_tokens, ln1g + l*D_, ln1b + l*D_, p_y);
        hgemm<<<dim3(384/64, M/128), 256, HG_SMEM>>>(p_y, Wqkv + (size_t)l*D_*3*D_,
                                                     nullptr, nullptr, p_qkv, M, 384, 128, 0);
        k_attn<<<dim3(N_/32, H_, B_), 128>>>(p_qkv, p_att);
        hgemm<<<dim3(128/64, M/128), 256, HG_SMEM>>>(p_att, Wo + (size_t)l*D_*D_,
                                                     bo + l*D_, p_tokens, p_tokens, M, 128, 128, 0);
        k_ln<<<M, 128>>>(p_tokens, ln2g + l*D_, ln2b + l*D_, p_y);
        hgemm<<<dim3(256/64, M/128), 256, HG_SMEM>>>(p_y, W1 + (size_t)l*D_*2*D_,
                                                     b1 + l*2*D_, nullptr, p_h1, M, 256, 128, 1);
        hgemm<<<dim3(128/64, M/128), 256, HG_SMEM>>>(p_h1, W2 + (size_t)l*2*D_*D_,
                                                     b2 + l*D_, p_tokens, p_tokens, M, 128, 256, 0);
    }

    k_dec  <<<(B_*N_*32 + 255)/256, 256>>>(dWc, dbc, dWf, dbf);
    k_fuse <<<(B_*OUT_*OUT_ + 255)/256, 256>>>();
    k_conv1<<<(B_*2*OUT_*OUT_ + 255)/256, 256>>>(fW1, fb1);
    k_conv2<<<(B_*OUT_*OUT_ + 255)/256, 256>>>(fW2, fb2, out);
}

// round 11
// speedup vs baseline: 4.5744x; 1.4769x over previous
#include <cuda_runtime.h>
#include <cuda_bf16.h>
#include <math.h>
#include <stdint.h>

// ---------------- problem constants ----------------
namespace {
constexpr int B_   = 8;
constexpr int IMG_ = 128;
constexpr int D_   = 128;
constexpr int H_   = 4;
constexpr int HD_  = 32;
constexpr int L_   = 2;
constexpr int NC_  = 256;   // 16x16 coarse tokens
constexpr int NF_  = 1024;  // 32x32 fine tokens
constexpr int N_   = 1280;  // NC+NF
constexpr int OUT_ = 32;
constexpr float SCALE_ = 0.17677669529663687f; // 32^-0.5
}

// ---------------- scratch (static device globals; no allocations) ----------------
__device__ float g_fine  [B_*NF_*D_];
__device__ float g_tokens[B_*N_*D_];
__device__ float g_y     [B_*N_*D_];
__device__ float g_qkv   [B_*N_*3*D_];
__device__ float g_att   [B_*N_*D_];
__device__ float g_h1    [B_*N_*2*D_];
__device__ float g_e     [B_*NF_];
__device__ int   g_mask  [B_*NF_];
__device__ int   g_order [B_*NF_];
__device__ int   g_ntrue [B_];
__device__ float g_c     [B_*NC_];
__device__ float g_fmap  [B_*NF_];
__device__ float g_fused [B_*2*OUT_*OUT_];
__device__ float g_hb    [B_*2*OUT_*OUT_];
// bf16 hi/lo packed K (key-major, all heads: 64 dpairs) and V (transposed per head)
__device__ uint32_t g_khi [B_*N_*64];
__device__ uint32_t g_klo [B_*N_*64];
__device__ uint32_t g_vthi[B_*H_*32*(N_/2)];
__device__ uint32_t g_vtlo[B_*H_*32*(N_/2)];

// ---------------- helpers ----------------
__device__ __forceinline__ uint32_t pkbf(__nv_bfloat16 a, __nv_bfloat16 b) {
    return (uint32_t)__bfloat16_as_ushort(a) | ((uint32_t)__bfloat16_as_ushort(b) << 16);
}
__device__ __forceinline__ void hilo2(float a, float b, uint32_t& h, uint32_t& l) {
    __nv_bfloat16 ha = __float2bfloat16(a), hb = __float2bfloat16(b);
    h = pkbf(ha, hb);
    l = pkbf(__float2bfloat16(a - __bfloat162float(ha)),
             __float2bfloat16(b - __bfloat162float(hb)));
}
__device__ __forceinline__ void mma16816(float* c, const uint32_t* a, const uint32_t* b) {
    asm volatile(
        "mma.sync.aligned.m16n8k16.row.col.f32.bf16.bf16.f32 "
        "{%0,%1,%2,%3}, {%4,%5,%6,%7}, {%8,%9}, {%0,%1,%2,%3};"
        : "+f"(c[0]), "+f"(c[1]), "+f"(c[2]), "+f"(c[3])
        : "r"(a[0]), "r"(a[1]), "r"(a[2]), "r"(a[3]), "r"(b[0]), "r"(b[1]));
}

// ---------------- patch embeds ----------------
__global__ void k_coarse(const float* __restrict__ x, const float* __restrict__ Wpc,
                         const float* __restrict__ bpc, const float* __restrict__ te) {
    __shared__ float sp[64];
    int blk = blockIdx.x;
    int b = blk >> 8, tok = blk & 255;
    int i = tok >> 4, j = tok & 15;
    int t = threadIdx.x;
    if (t < 64) {
        int pr = t >> 3, pc = t & 7;
        sp[t] = x[(b*IMG_ + i*8 + pr)*IMG_ + j*8 + pc];
    }
    __syncthreads();
    float acc = 0.f;
    #pragma unroll
    for (int p = 0; p < 64; p++) acc += sp[p] * Wpc[p*D_ + t];
    g_tokens[((size_t)b*N_ + tok)*D_ + t] = acc + bpc[t] + te[t];
}

__global__ void k_fine(const float* __restrict__ x, const float* __restrict__ Wpf,
                       const float* __restrict__ bpf) {
    __shared__ float sp[16];
    int blk = blockIdx.x;
    int b = blk >> 10, tok = blk & 1023;
    int i = tok >> 5, j = tok & 31;
    int t = threadIdx.x;
    if (t < 16) {
        int pr = t >> 2, pc = t & 3;
        sp[t] = x[(b*IMG_ + i*4 + pr)*IMG_ + j*4 + pc];
    }
    __syncthreads();
    float acc = 0.f;
    #pragma unroll
    for (int p = 0; p < 16; p++) acc += sp[p] * Wpf[p*D_ + t];
    g_fine[((size_t)b*NF_ + tok)*D_ + t] = acc + bpf[t];
}

// ---------------- edge map ----------------
__device__ __forceinline__ float xat(const float* x, int b, int y, int c) {
    if ((unsigned)y >= (unsigned)IMG_ || (unsigned)c >= (unsigned)IMG_) return 0.f;
    return x[(b*IMG_ + y)*IMG_ + c];
}

__global__ void k_edge(const float* __restrict__ x) {
    int idx = blockIdx.x*blockDim.x + threadIdx.x;
    if (idx >= B_*NF_) return;
    int b = idx >> 10, cell = idx & 1023;
    int yi = cell >> 5, xi = cell & 31;
    float acc = 0.f;
    for (int dy = 0; dy < 4; dy++)
    for (int dx = 0; dx < 4; dx++) {
        int py = yi*4 + dy, px = xi*4 + dx;
        float a  = xat(x,b,py-1,px-1), bv = xat(x,b,py-1,px), c  = xat(x,b,py-1,px+1);
        float d  = xat(x,b,py  ,px-1),                         e2 = xat(x,b,py  ,px+1);
        float f  = xat(x,b,py+1,px-1), g  = xat(x,b,py+1,px), h2 = xat(x,b,py+1,px+1);
        float gx = -a + c - 2.f*d + 2.f*e2 - f + h2;
        float gy = -a - 2.f*bv - c + f + 2.f*g + h2;
        acc += sqrtf(gx*gx + gy*gy);
    }
    g_e[idx] = acc * (1.f/16.f);
}

__global__ void k_mask() {
    int b = blockIdx.x, t = threadIdx.x;
    __shared__ float sh[256];
    float s = 0.f;
    for (int i = t; i < NF_; i += 256) s += g_e[b*NF_ + i];
    sh[t] = s; __syncthreads();
    for (int o = 128; o; o >>= 1) { if (t < o) sh[t] += sh[t+o]; __syncthreads(); }
    float mean = sh[0] * (1.f/NF_);
    for (int i = t; i < NF_; i += 256)
        g_mask[b*NF_ + i] = (g_e[b*NF_ + i] > mean) ? 1 : 0;
}

__global__ void k_order() {
    int b = blockIdx.x, t = threadIdx.x;
    __shared__ int sh[1024];
    int m = g_mask[b*NF_ + t];
    sh[t] = m; __syncthreads();
    for (int o = 1; o < 1024; o <<= 1) {
        int v = (t >= o) ? sh[t-o] : 0;
        __syncthreads();
        sh[t] += v;
        __syncthreads();
    }
    int incl = sh[t];
    int total = sh[1023];
    int pos = m ? (incl - 1) : (total + t - incl);
    g_order[b*NF_ + pos] = t;
    if (t == 0) g_ntrue[b] = total;
}

__global__ void k_assemble(const float* __restrict__ te) {
    int blk = blockIdx.x;
    int b = blk >> 10, pos = blk & 1023;
    int t = threadIdx.x;
    float v = te[D_ + t];
    if (pos < g_ntrue[b])
        v += g_fine[((size_t)b*NF_ + g_order[b*NF_ + pos])*D_ + t];
    g_tokens[((size_t)b*N_ + NC_ + pos)*D_ + t] = v;
}

// ---------------- layernorm ----------------
__global__ void k_ln(const float* __restrict__ in, const float* __restrict__ g,
                     const float* __restrict__ bb, float* __restrict__ out) {
    int row = blockIdx.x, t = threadIdx.x;
    int b = row / N_;
    if (row - b*N_ > NC_ + g_ntrue[b]) return;
    float v = in[(size_t)row*D_ + t];
    float s = v, q = v*v;
    #pragma unroll
    for (int o = 16; o; o >>= 1) {
        s += __shfl_xor_sync(~0u, s, o);
        q += __shfl_xor_sync(~0u, q, o);
    }
    __shared__ float ss[4], sq[4];
    int w = t >> 5, lane = t & 31;
    if (lane == 0) { ss[w] = s; sq[w] = q; }
    __syncthreads();
    s = ss[0]+ss[1]+ss[2]+ss[3];
    q = sq[0]+sq[1]+sq[2]+sq[3];
    float mean = s * (1.f/D_);
    float var  = q * (1.f/D_) - mean*mean;
    out[(size_t)row*D_ + t] = (v - mean) * rsqrtf(var + 1e-5f) * g[t] + bb[t];
}

// ---------------- tensor-core GEMM (validated R7) ----------------
#define HG_SMEM 52224
__global__ __launch_bounds__(256) void hgemm(
    const float* __restrict__ A, const float* __restrict__ Bw,
    const float* __restrict__ bias, const float* __restrict__ res,
    float* __restrict__ C, int M, int Nn, int K, int act)
{
    int m0 = blockIdx.y*128, n0 = blockIdx.x*64;
    {
        int bb = m0 / N_;
        if (m0 - bb*N_ > NC_ + g_ntrue[bb]) return;
    }
    extern __shared__ __align__(16) uint32_t sm[];
    uint32_t* Ahi = sm;
    uint32_t* Alo = sm + 4352;
    uint32_t* Bhi = sm + 8704;
    uint32_t* Blo = sm + 10880;

    int t = threadIdx.x, wid = t >> 5, lane = t & 31;
    int wm = wid >> 1, wn = wid & 1;
    int grp = lane >> 2, tig = lane & 3;

    float acc[2][4][4];
    #pragma unroll
    for (int i = 0; i < 2; i++)
        #pragma unroll
        for (int j = 0; j < 4; j++)
            #pragma unroll
            for (int q = 0; q < 4; q++) acc[i][j][q] = 0.f;

    int nchunk = K >> 6;
    for (int kc = 0; kc < nchunk; kc++) {
        #pragma unroll 4
        for (int it = 0; it < 16; it++) {
            int idx = it*256 + t;
            int row = idx >> 5, p = idx & 31;
            float2 v = *(const float2*)(A + (size_t)(m0+row)*K + kc*64 + p*2);
            hilo2(v.x, v.y, Ahi[row*34 + p], Alo[row*34 + p]);
        }
        #pragma unroll 4
        for (int it = 0; it < 8; it++) {
            int idx = it*256 + t;
            int p = idx >> 6, n = idx & 63;
            float v0 = Bw[(size_t)(kc*64 + p*2    )*Nn + n0 + n];
            float v1 = Bw[(size_t)(kc*64 + p*2 + 1)*Nn + n0 + n];
            hilo2(v0, v1, Bhi[n*34 + p], Blo[n*34 + p]);
        }
        __syncthreads();

        #pragma unroll
        for (int s = 0; s < 4; s++) {
            int pb = s*8;
            uint32_t ah[2][4], al[2][4], bh[4][2], bl[4][2];
            #pragma unroll
            for (int mt = 0; mt < 2; mt++) {
                int r = (wm*32 + mt*16 + grp)*34;
                ah[mt][0] = Ahi[r + pb + tig];          al[mt][0] = Alo[r + pb + tig];
                ah[mt][1] = Ahi[r + 8*34 + pb + tig];   al[mt][1] = Alo[r + 8*34 + pb + tig];
                ah[mt][2] = Ahi[r + pb + 4 + tig];      al[mt][2] = Alo[r + pb + 4 + tig];
                ah[mt][3] = Ahi[r + 8*34 + pb + 4 + tig]; al[mt][3] = Alo[r + 8*34 + pb + 4 + tig];
            }
            #pragma unroll
            for (int nt = 0; nt < 4; nt++) {
                int r = (wn*32 + nt*8 + grp)*34;
                bh[nt][0] = Bhi[r + pb + tig];     bl[nt][0] = Blo[r + pb + tig];
                bh[nt][1] = Bhi[r + pb + 4 + tig]; bl[nt][1] = Blo[r + pb + 4 + tig];
            }
            #pragma unroll
            for (int mt = 0; mt < 2; mt++)
                #pragma unroll
                for (int nt = 0; nt < 4; nt++) {
                    mma16816(acc[mt][nt], ah[mt], bh[nt]);
                    mma16816(acc[mt][nt], ah[mt], bl[nt]);
                    mma16816(acc[mt][nt], al[mt], bh[nt]);
                }
        }
        __syncthreads();
    }

    #pragma unroll
    for (int mt = 0; mt < 2; mt++) {
        #pragma unroll
        for (int nt = 0; nt < 4; nt++) {
            int col = n0 + wn*32 + nt*8 + tig*2;
            #pragma unroll
            for (int half = 0; half < 2; half++) {
                int row = m0 + wm*32 + mt*16 + grp + half*8;
                float v0 = acc[mt][nt][half*2], v1 = acc[mt][nt][half*2+1];
                if (bias) { v0 += bias[col]; v1 += bias[col+1]; }
                if (act == 1) {
                    v0 = 0.5f*v0*(1.f + erff(v0*0.70710678118654752f));
                    v1 = 0.5f*v1*(1.f + erff(v1*0.70710678118654752f));
                }
                if (res) {
                    float2 rv = *(const float2*)(res + (size_t)row*Nn + col);
                    v0 += rv.x; v1 += rv.y;
                }
                *(float2*)(C + (size_t)row*Nn + col) = make_float2(v0, v1);
            }
        }
    }
}

// ---------------- K/V preconvert (once per layer) ----------------
// K: packed dpairs, key-major, all heads: g_khi[(b*N+key)*64 + dp], dp = h*16 + kp
__global__ void k_prepk(const float* __restrict__ qkv) {
    int idx = blockIdx.x*blockDim.x + threadIdx.x;   // over B*N*64
    if (idx >= B_*N_*64) return;
    int keyg = idx >> 6, dp = idx & 63;
    float2 v = *(const float2*)(qkv + (size_t)keyg*384 + 128 + dp*2);
    hilo2(v.x, v.y, g_khi[idx], g_klo[idx]);
}

// V transposed per head: g_vthi[((b*H+h)*32 + d)*640 + kp], kp packs keys (2kp, 2kp+1)
__global__ __launch_bounds__(128) void k_prepv(const float* __restrict__ qkv) {
    __shared__ uint16_t shi[32*65], slo[32*65];
    int blk = blockIdx.x;            // b*80 + h*20 + kt
    int b = blk / 80, r = blk % 80;
    int h = r / 20, kt = r % 20;
    int t = threadIdx.x;
    #pragma unroll
    for (int it = 0; it < 16; it++) {
        int idx = it*128 + t;        // 64 keys x 32 d
        int key = idx >> 5, d = idx & 31;
        float v = qkv[((size_t)(b*N_) + kt*64 + key)*384 + 256 + h*32 + d];
        __nv_bfloat16 hi = __float2bfloat16(v);
        shi[d*65 + key] = __bfloat16_as_ushort(hi);
        slo[d*65 + key] = __bfloat16_as_ushort(__float2bfloat16(v - __bfloat162float(hi)));
    }
    __syncthreads();
    #pragma unroll
    for (int it = 0; it < 8; it++) {
        int idx = it*128 + t;        // 32 d x 32 kp
        int d = idx >> 5, kp = idx & 31;
        size_t o = ((size_t)(b*H_ + h)*32 + d)*640 + kt*32 + kp;
        g_vthi[o] = (uint32_t)shi[d*65 + kp*2] | ((uint32_t)shi[d*65 + kp*2 + 1] << 16);
        g_vtlo[o] = (uint32_t)slo[d*65 + kp*2] | ((uint32_t)slo[d*65 + kp*2 + 1] << 16);
    }
}

// ---------------- tensor-core flash attention with pad dedup ----------------
// 64 queries/block, 4 warps x 16 rows. hd=32. Key tiles of 64.
__global__ __launch_bounds__(128) void k_attn_tc(const float* __restrict__ qkv,
                                                 float* __restrict__ out) {
    __shared__ uint32_t Kh[64*17], Kl[64*17], Vh[32*34], Vl[32*34];
    int b = blockIdx.z, h = blockIdx.y, q0 = blockIdx.x*64;
    int ntrue = g_ntrue[b];
    int rep = NC_ + ntrue;                   // == N_ when no pads
    if (q0 > rep) return;
    float wpad = (float)(NF_ - ntrue);
    int nkv = (rep < N_) ? (rep + 1) : N_;

    int t = threadIdx.x, w = t >> 5, lane = t & 31;
    int grp = lane >> 2, tig = lane & 3;
    int row0 = q0 + w*16 + grp, row1 = row0 + 8;

    // Q fragments (SCALE folded), hi/lo: 2 k-steps
    uint32_t qh[2][4], ql[2][4];
    #pragma unroll
    for (int s = 0; s < 2; s++) {
        int p0 = 8*s + tig, p1 = 8*s + tig + 4;
        const float* q0p = qkv + (size_t)(b*N_ + row0)*384 + h*32;
        const float* q1p = qkv + (size_t)(b*N_ + row1)*384 + h*32;
        float2 v;
        v = *(const float2*)(q0p + p0*2); hilo2(v.x*SCALE_, v.y*SCALE_, qh[s][0], ql[s][0]);
        v = *(const float2*)(q1p + p0*2); hilo2(v.x*SCALE_, v.y*SCALE_, qh[s][1], ql[s][1]);
        v = *(const float2*)(q0p + p1*2); hilo2(v.x*SCALE_, v.y*SCALE_, qh[s][2], ql[s][2]);
        v = *(const float2*)(q1p + p1*2); hilo2(v.x*SCALE_, v.y*SCALE_, qh[s][3], ql[s][3]);
    }

    float m0 = -1e30f, m1 = -1e30f, s0 = 0.f, s1 = 0.f;
    float o[4][4];
    #pragma unroll
    for (int i = 0; i < 4; i++)
        #pragma unroll
        for (int j = 0; j < 4; j++) o[i][j] = 0.f;

    for (int k0 = 0; k0 < nkv; k0 += 64) {
        __syncthreads();
        // stage K (head slice: kp = h*16..h*16+15) and Vt
        #pragma unroll
        for (int it = 0; it < 8; it++) {
            int idx = it*128 + t;            // 64 keys x 16 kp
            int key = idx >> 4, kp = idx & 15;
            size_t go = (size_t)(b*N_ + k0 + key)*64 + h*16 + kp;
            Kh[key*17 + kp] = g_khi[go];
            Kl[key*17 + kp] = g_klo[go];
        }
        #pragma unroll
        for (int it = 0; it < 8; it++) {
            int idx = it*128 + t;            // 32 d x 32 kp
            int d = idx >> 5, kp = idx & 31;
            size_t go = ((size_t)(b*H_ + h)*32 + d)*640 + (k0 >> 1) + kp;
            Vh[d*34 + kp] = g_vthi[go];
            Vl[d*34 + kp] = g_vtlo[go];
        }
        __syncthreads();

        // S = Q*K^T  (8 n-tiles of 8 keys)
        float S[8][4];
        #pragma unroll
        for (int nt = 0; nt < 8; nt++) {
            S[nt][0] = S[nt][1] = S[nt][2] = S[nt][3] = 0.f;
            #pragma unroll
            for (int s = 0; s < 2; s++) {
                uint32_t bh[2], bl[2];
                int r = (nt*8 + grp)*17;
                bh[0] = Kh[r + s*8 + tig];     bl[0] = Kl[r + s*8 + tig];
                bh[1] = Kh[r + s*8 + 4 + tig]; bl[1] = Kl[r + s*8 + 4 + tig];
                mma16816(S[nt], qh[s], bh);
                mma16816(S[nt], qh[s], bl);
                mma16816(S[nt], ql[s], bh);
            }
        }
        // mask cols beyond rep
        #pragma unroll
        for (int nt = 0; nt < 8; nt++) {
            int c0 = k0 + nt*8 + tig*2, c1 = c0 + 1;
            if (c0 > rep) { S[nt][0] = -1e30f; S[nt][2] = -1e30f; }
            if (c1 > rep) { S[nt][1] = -1e30f; S[nt][3] = -1e30f; }
        }
        // row maxima (16 cols per thread per row, then quad shfl)
        float mx0 = -1e30f, mx1 = -1e30f;
        #pragma unroll
        for (int nt = 0; nt < 8; nt++) {
            mx0 = fmaxf(mx0, fmaxf(S[nt][0], S[nt][1]));
            mx1 = fmaxf(mx1, fmaxf(S[nt][2], S[nt][3]));
        }
        mx0 = fmaxf(mx0, __shfl_xor_sync(~0u, mx0, 1));
        mx0 = fmaxf(mx0, __shfl_xor_sync(~0u, mx0, 2));
        mx1 = fmaxf(mx1, __shfl_xor_sync(~0u, mx1, 1));
        mx1 = fmaxf(mx1, __shfl_xor_sync(~0u, mx1, 2));
        float mn0 = fmaxf(m0, mx0), mn1 = fmaxf(m1, mx1);
        float f0 = __expf(m0 - mn0), f1 = __expf(m1 - mn1);
        m0 = mn0; m1 = mn1;
        s0 *= f0; s1 *= f1;
        #pragma unroll
        for (int i = 0; i < 4; i++) {
            o[i][0] *= f0; o[i][1] *= f0; o[i][2] *= f1; o[i][3] *= f1;
        }
        // p = exp(S - m), pad weighting, row sums
        float rs0 = 0.f, rs1 = 0.f;
        #pragma unroll
        for (int nt = 0; nt < 8; nt++) {
            int c0 = k0 + nt*8 + tig*2, c1 = c0 + 1;
            float p0 = (c0 > rep) ? 0.f : __expf(S[nt][0] - m0);
            float p1 = (c1 > rep) ? 0.f : __expf(S[nt][1] - m0);
            float p2 = (c0 > rep) ? 0.f : __expf(S[nt][2] - m1);
            float p3 = (c1 > rep) ? 0.f : __expf(S[nt][3] - m1);
            if (c0 == rep) { p0 *= wpad; p2 *= wpad; }
            if (c1 == rep) { p1 *= wpad; p3 *= wpad; }
            S[nt][0] = p0; S[nt][1] = p1; S[nt][2] = p2; S[nt][3] = p3;
            rs0 += p0 + p1; rs1 += p2 + p3;
        }
        rs0 += __shfl_xor_sync(~0u, rs0, 1); rs0 += __shfl_xor_sync(~0u, rs0, 2);
        rs1 += __shfl_xor_sync(~0u, rs1, 1); rs1 += __shfl_xor_sync(~0u, rs1, 2);
        s0 += rs0; s1 += rs1;

        // O += P*V : 4 k-steps over keys, 4 d-tiles
        #pragma unroll
        for (int s2 = 0; s2 < 4; s2++) {
            uint32_t ph[4], pl[4];
            hilo2(S[2*s2  ][0], S[2*s2  ][1], ph[0], pl[0]);
            hilo2(S[2*s2  ][2], S[2*s2  ][3], ph[1], pl[1]);
            hilo2(S[2*s2+1][0], S[2*s2+1][1], ph[2], pl[2]);
            hilo2(S[2*s2+1][2], S[2*s2+1][3], ph[3], pl[3]);
            #pragma unroll
            for (int vt = 0; vt < 4; vt++) {
                uint32_t bh[2], bl[2];
                int r = (vt*8 + grp)*34;
                bh[0] = Vh[r + s2*8 + tig];     bl[0] = Vl[r + s2*8 + tig];
                bh[1] = Vh[r + s2*8 + 4 + tig]; bl[1] = Vl[r + s2*8 + 4 + tig];
                mma16816(o[vt], ph, bh);
                mma16816(o[vt], ph, bl);
                mma16816(o[vt], pl, bh);
            }
        }
    }

    float inv0 = 1.f / s0, inv1 = 1.f / s1;
    #pragma unroll
    for (int vt = 0; vt < 4; vt++) {
        int col = h*32 + vt*8 + tig*2;
        *(float2*)(out + (size_t)(b*N_ + row0)*D_ + col) = make_float2(o[vt][0]*inv0, o[vt][1]*inv0);
        *(float2*)(out + (size_t)(b*N_ + row1)*D_ + col) = make_float2(o[vt][2]*inv1, o[vt][3]*inv1);
    }
}

// ---------------- decoder heads ----------------
__global__ void k_dec(const float* __restrict__ dWc, const float* __restrict__ dbc,
                      const float* __restrict__ dWf, const float* __restrict__ dbf) {
    int gid  = blockIdx.x*blockDim.x + threadIdx.x;
    int warp = gid >> 5;
    int lane = threadIdx.x & 31;
    if (warp >= B_*N_) return;
    int b = warp / N_, i = warp % N_;
    bool isC = (i < NC_);
    if (!isC && (i - NC_) >= g_ntrue[b]) {
        if (lane == 0) g_fmap[b*NF_ + g_order[b*NF_ + (i - NC_)]] = 0.f;
        return;
    }
    const float* tok = g_tokens + (size_t)warp*D_;
    const float* w = isC ? dWc : dWf;
    float a = 0.f;
    for (int d = lane; d < D_; d += 32) a += tok[d]*w[d];
    #pragma unroll
    for (int o = 16; o; o >>= 1) a += __shfl_xor_sync(~0u, a, o);
    if (lane == 0) {
        if (isC) g_c[b*NC_ + i] = a + dbc[0];
        else     g_fmap[b*NF_ + g_order[b*NF_ + (i - NC_)]] = a + dbf[0];
    }
}

__global__ void k_fuse() {
    int idx = blockIdx.x*blockDim.x + threadIdx.x;
    if (idx >= B_*OUT_*OUT_) return;
    int b = idx >> 10, oy = (idx >> 5) & 31, ox = idx & 31;
    float fy = oy * (15.f/31.f), fx = ox * (15.f/31.f);
    int y0 = (int)floorf(fy), x0 = (int)floorf(fx);
    int y1 = min(y0+1, 15), x1 = min(x0+1, 15);
    float wy = fy - y0, wx = fx - x0;
    const float* c = g_c + b*NC_;
    float cu = c[y0*16+x0]*(1.f-wy)*(1.f-wx) + c[y0*16+x1]*(1.f-wy)*wx
             + c[y1*16+x0]*wy*(1.f-wx)       + c[y1*16+x1]*wy*wx;
    g_fused[((b*2+0)*OUT_ + oy)*OUT_ + ox] = cu;
    g_fused[((b*2+1)*OUT_ + oy)*OUT_ + ox] = g_fmap[b*NF_ + oy*32 + ox];
}

__global__ void k_conv1(const float* __restrict__ w, const float* __restrict__ bias) {
    int idx = blockIdx.x*blockDim.x + threadIdx.x;
    if (idx >= B_*2*OUT_*OUT_) return;
    int ox = idx & 31, oy = (idx >> 5) & 31, co = (idx >> 10) & 1, b = idx >> 11;
    float a = bias[co];
    for (int ci = 0; ci < 2; ci++)
    for (int ky = 0; ky < 3; ky++)
    for (int kx = 0; kx < 3; kx++) {
        int y = oy + ky - 1, x2 = ox + kx - 1;
        if ((unsigned)y < 32u && (unsigned)x2 < 32u)
            a += g_fused[((b*2+ci)*OUT_ + y)*OUT_ + x2] * w[((co*2+ci)*3 + ky)*3 + kx];
    }
    g_hb[((b*2+co)*OUT_ + oy)*OUT_ + ox] = fmaxf(a, 0.f);
}

__global__ void k_conv2(const float* __restrict__ w, const float* __restrict__ bias,
                        float* __restrict__ out) {
    int idx = blockIdx.x*blockDim.x + threadIdx.x;
    if (idx >= B_*OUT_*OUT_) return;
    int ox = idx & 31, oy = (idx >> 5) & 31, b = idx >> 10;
    float a = bias[0];
    for (int ci = 0; ci < 2; ci++)
    for (int ky = 0; ky < 3; ky++)
    for (int kx = 0; kx < 3; kx++) {
        int y = oy + ky - 1, x2 = ox + kx - 1;
        if ((unsigned)y < 32u && (unsigned)x2 < 32u)
            a += g_hb[((b*2+ci)*OUT_ + y)*OUT_ + x2] * w[(ci*3 + ky)*3 + kx];
    }
    out[b*OUT_*OUT_ + oy*OUT_ + ox] = a;
}

// ---------------- host orchestration ----------------
extern "C" void kernel_launch(void* const* d_in, const int* in_sizes, int n_in,
                              void* d_out, int out_size) {
    const float* x    = (const float*)d_in[0];
    const float* Wpc  = (const float*)d_in[1];
    const float* bpc  = (const float*)d_in[2];
    const float* Wpf  = (const float*)d_in[3];
    const float* bpf  = (const float*)d_in[4];
    const float* te   = (const float*)d_in[5];
    const float* ln1g = (const float*)d_in[6];
    const float* ln1b = (const float*)d_in[7];
    const float* Wqkv = (const float*)d_in[8];
    const float* Wo   = (const float*)d_in[9];
    const float* bo   = (const float*)d_in[10];
    const float* ln2g = (const float*)d_in[11];
    const float* ln2b = (const float*)d_in[12];
    const float* W1   = (const float*)d_in[13];
    const float* b1   = (const float*)d_in[14];
    const float* W2   = (const float*)d_in[15];
    const float* b2   = (const float*)d_in[16];
    const float* dWc  = (const float*)d_in[17];
    const float* dbc  = (const float*)d_in[18];
    const float* dWf  = (const float*)d_in[19];
    const float* dbf  = (const float*)d_in[20];
    const float* fW1  = (const float*)d_in[21];
    const float* fb1  = (const float*)d_in[22];
    const float* fW2  = (const float*)d_in[23];
    const float* fb2  = (const float*)d_in[24];
    float* out = (float*)d_out;

    float *p_tokens, *p_y, *p_qkv, *p_att, *p_h1;
    cudaGetSymbolAddress((void**)&p_tokens, g_tokens);
    cudaGetSymbolAddress((void**)&p_y,      g_y);
    cudaGetSymbolAddress((void**)&p_qkv,    g_qkv);
    cudaGetSymbolAddress((void**)&p_att,    g_att);
    cudaGetSymbolAddress((void**)&p_h1,     g_h1);

    cudaFuncSetAttribute(hgemm, cudaFuncAttributeMaxDynamicSharedMemorySize, HG_SMEM);

    const int M = B_ * N_; // 10240

    k_coarse  <<<B_*NC_, 128>>>(x, Wpc, bpc, te);
    k_fine    <<<B_*NF_, 128>>>(x, Wpf, bpf);
    k_edge    <<<(B_*NF_ + 255)/256, 256>>>(x);
    k_mask    <<<B_, 256>>>();
    k_order   <<<B_, 1024>>>();
    k_assemble<<<B_*NF_, 128>>>(te);

    for (int l = 0; l < L_; l++) {
        k_ln<<<M, 128>>>(p_tokens, ln1g + l*D_, ln1b + l*D_, p_y);
        hgemm<<<dim3(384/64, M/128), 256, HG_SMEM>>>(p_y, Wqkv + (size_t)l*D_*3*D_,
                                                     nullptr, nullptr, p_qkv, M, 384, 128, 0);
        k_prepk<<<(B_*N_*64 + 255)/256, 256>>>(p_qkv);
        k_prepv<<<B_*H_*20, 128>>>(p_qkv);
        k_attn_tc<<<dim3(N_/64, H_, B_), 128>>>(p_qkv, p_att);
        hgemm<<<dim3(128/64, M/128), 256, HG_SMEM>>>(p_att, Wo + (size_t)l*D_*D_,
                                                     bo + l*D_, p_tokens, p_tokens, M, 128, 128, 0);
        k_ln<<<M, 128>>>(p_tokens, ln2g + l*D_, ln2b + l*D_, p_y);
        hgemm<<<dim3(256/64, M/128), 256, HG_SMEM>>>(p_y, W1 + (size_t)l*D_*2*D_,
                                                     b1 + l*2*D_, nullptr, p_h1, M, 256, 128, 1);
        hgemm<<<dim3(128/64, M/128), 256, HG_SMEM>>>(p_h1, W2 + (size_t)l*2*D_*D_,
                                                     b2 + l*D_, p_tokens, p_tokens, M, 128, 256, 0);
    }

    k_dec  <<<(B_*N_*32 + 255)/256, 256>>>(dWc, dbc, dWf, dbf);
    k_fuse <<<(B_*OUT_*OUT_ + 255)/256, 256>>>();
    k_conv1<<<(B_*2*OUT_*OUT_ + 255)/256, 256>>>(fW1, fb1);
    k_conv2<<<(B_*OUT_*OUT_ + 255)/256, 256>>>(fW2, fb2, out);
}